// round 5
// baseline (speedup 1.0000x reference)
#include <cuda_runtime.h>
#include <stdint.h>

#define NP   8192
#define KNN  64
#define EPSF 1e-7f
typedef unsigned long long ull;

// ------------------------- static scratch -------------------------
__device__ float g_px[NP], g_py[NP], g_pz[NP], g_vn[NP];
__device__ __align__(16) float4 g_pt4[NP];
__device__ ull   g_gmax, g_gmin;
__device__ int   g_idx[NP * KNN];
__device__ __align__(16) float g_feat[NP * KNN * 4];
__device__ __align__(16) float g_fd[NP * 4];
__device__ __align__(16) float g_emb[192 * NP];
__device__ __align__(16) float g_y1[64 * NP];
__device__ __align__(16) float g_y3[256 * NP];
__device__ __align__(16) float g_y4[1024 * NP];
__device__ float g_sc1[64],  g_sh1[64];
__device__ float g_sc2[192], g_sh2[192];
__device__ float g_sc3[256], g_sh3[256];
__device__ float g_sc4[1024], g_sh4[1024];

// ------------------------- f32x2 helpers -------------------------
__device__ __forceinline__ ull ffma2(ull a, ull b, ull c) {
    ull d;
    asm("fma.rn.f32x2 %0, %1, %2, %3;" : "=l"(d) : "l"(a), "l"(b), "l"(c));
    return d;
}
__device__ __forceinline__ ull pack2(float x, float y) {
    ull d;
    asm("mov.b64 %0, {%1, %2};" : "=l"(d) : "f"(x), "f"(y));
    return d;
}
__device__ __forceinline__ void unpack2(ull v, float& x, float& y) {
    asm("mov.b64 {%0, %1}, %2;" : "=f"(x), "=f"(y) : "l"(v));
}

// ------------------------- prep -------------------------
__global__ void prep_kernel(const float* __restrict__ pts) {
    int i = blockIdx.x * blockDim.x + threadIdx.x;
    if (i == 0) { g_gmax = 0ULL; g_gmin = ~0ULL; }
    if (i < 64) { g_sc2[i] = 1.0f; g_sh2[i] = 0.0f; }   // identity BN for emb_up rows
    if (i < NP) {
        float x = pts[3 * i], y = pts[3 * i + 1], z = pts[3 * i + 2];
        g_px[i] = x; g_py[i] = y; g_pz[i] = z;
        float rr = x * x + y * y + z * z;
        g_vn[i] = sqrtf(rr);
        g_pt4[i] = make_float4(x, y, z, rr);
    }
}

// ------------------------- KNN rank-64 selection (fully deterministic) ----------
__global__ void __launch_bounds__(256) knn_kernel() {
    const int i = blockIdx.x, tid = threadIdx.x;
    const int lane = tid & 31, warp = tid >> 5;
    __shared__ int wsum[16];
    __shared__ int wcntL[8], wcntE[8];
    __shared__ ull cmin;
    __shared__ int nact;
    __shared__ int eqbuf[256];
    __shared__ unsigned short actkey[2048];

    float4 q4 = g_pt4[i];
    unsigned key[32];
#pragma unroll
    for (int s = 0; s < 32; s++) {
        float4 p = g_pt4[s * 256 + tid];
        float d = q4.w - 2.0f * (q4.x * p.x + q4.y * p.y + q4.z * p.z) + p.w;
        unsigned u = __float_as_uint(d);
        key[s] = u ^ ((u & 0x80000000u) ? 0xFFFFFFFFu : 0x80000000u);
    }
    if (tid == 0) { cmin = ~0ULL; nact = 0; }
    __syncthreads();

    // global min (key, index) = center
    {
        ull lm = ~0ULL;
#pragma unroll
        for (int s = 0; s < 32; s++) {
            ull pk = (((ull)key[s]) << 32) | (unsigned)(s * 256 + tid);
            lm = (pk < lm) ? pk : lm;
        }
        atomicMin(&cmin, lm);
    }

    unsigned v = 0u;
    int cless = 0;
    // stage 1: bits 31..16 over register keys, one barrier/round (parity banks)
    for (int b = 31; b >= 16; b--) {
        unsigned cand = v | (1u << b);
        int cnt = 0;
#pragma unroll
        for (int s = 0; s < 32; s++) cnt += (key[s] < cand) ? 1 : 0;
        cnt = __reduce_add_sync(0xFFFFFFFFu, cnt);
        int bank = (b & 1) << 3;
        if (lane == 0) wsum[bank + warp] = cnt;
        __syncthreads();
        int tot = 0;
#pragma unroll
        for (int w = 0; w < 8; w++) tot += wsum[bank + w];
        if (tot < KNN) { v = cand; cless = tot; }
    }

    // compact candidates with matching high-16 prefix
    unsigned p16 = v >> 16;
#pragma unroll
    for (int s = 0; s < 32; s++) {
        if ((key[s] >> 16) == p16) {
            int a = atomicAdd(&nact, 1);
            if (a < 2048) actkey[a] = (unsigned short)(key[s] & 0xFFFFu);
        }
    }
    __syncthreads();
    int na = nact;
    int base = cless;

    if (na <= 2048) {
        for (int b = 15; b >= 0; b--) {
            unsigned cl = (v | (1u << b)) & 0xFFFFu;
            int cnt = 0;
            for (int t = tid; t < na; t += 256) cnt += (actkey[t] < cl) ? 1 : 0;
            cnt = __reduce_add_sync(0xFFFFFFFFu, cnt);
            int bank = (b & 1) << 3;
            if (lane == 0) wsum[bank + warp] = cnt;
            __syncthreads();
            int tot = base;
#pragma unroll
            for (int w = 0; w < 8; w++) tot += wsum[bank + w];
            if (tot < KNN) { v |= (1u << b); cless = tot; }
        }
    } else {
        for (int b = 15; b >= 0; b--) {
            unsigned cand = v | (1u << b);
            int cnt = 0;
#pragma unroll
            for (int s = 0; s < 32; s++) cnt += (key[s] < cand) ? 1 : 0;
            cnt = __reduce_add_sync(0xFFFFFFFFu, cnt);
            int bank = (b & 1) << 3;
            if (lane == 0) wsum[bank + warp] = cnt;
            __syncthreads();
            int tot = 0;
#pragma unroll
            for (int w = 0; w < 8; w++) tot += wsum[bank + w];
            if (tot < KNN) { v = cand; cless = tot; }
        }
    }

    int center = (int)(cmin & 0xFFFFFFFFu);
    unsigned ckey = (unsigned)(cmin >> 32);
    int startEq = (ckey == v) ? (cless + 1) : cless;

    // deterministic gather: per-warp counts, then ballot-scan in (warp, s, lane) order
    {
        int cl2 = 0, ce2 = 0;
#pragma unroll
        for (int s = 0; s < 32; s++) {
            int n = s * 256 + tid;
            unsigned kk = key[s];
            cl2 += (kk < v && n != center) ? 1 : 0;
            ce2 += (kk == v && n != center) ? 1 : 0;
        }
        cl2 = __reduce_add_sync(0xFFFFFFFFu, cl2);
        ce2 = __reduce_add_sync(0xFFFFFFFFu, ce2);
        if (lane == 0) { wcntL[warp] = cl2; wcntE[warp] = ce2; }
        __syncthreads();
        int offL = 0, offE = 0;
        for (int w = 0; w < warp; w++) { offL += wcntL[w]; offE += wcntE[w]; }
        unsigned lt = (1u << lane) - 1u;
#pragma unroll
        for (int s = 0; s < 32; s++) {
            int n = s * 256 + tid;
            unsigned kk = key[s];
            bool pl = (kk < v) && (n != center);
            bool pe = (kk == v) && (n != center);
            unsigned ml = __ballot_sync(0xFFFFFFFFu, pl);
            unsigned me = __ballot_sync(0xFFFFFFFFu, pe);
            if (pl) g_idx[i * KNN + 1 + offL + __popc(ml & lt)] = n;
            if (pe) { int p = offE + __popc(me & lt); if (p < 256) eqbuf[p] = n; }
            offL += __popc(ml); offE += __popc(me);
        }
    }
    __syncthreads();
    if (tid == 0) {
        g_idx[i * KNN] = center;
        int neq = 0;
        for (int w = 0; w < 8; w++) neq += wcntE[w];
        int q = KNN - startEq;               // equals to take, smallest indices first
        int m = neq; if (m > 256) m = 256;
        for (int a = 0; a < q; a++) {
            int bi = a;
            for (int bj = a + 1; bj < m; bj++)
                if (eqbuf[bj] < eqbuf[bi]) bi = bj;
            int t = eqbuf[a]; eqbuf[a] = eqbuf[bi]; eqbuf[bi] = t;
            g_idx[i * KNN + startEq + a] = eqbuf[a];
        }
    }
}

// ------------------ per-query rotation-invariant KNN features ------------------
__global__ void __launch_bounds__(64) featknn_kernel() {
    int i = blockIdx.x, k = threadIdx.x;
    __shared__ float sx[64], sy[64], sz[64];
    __shared__ ull sred[64];
    __shared__ float rx[64], ry[64], rz[64];

    int j  = g_idx[i * KNN + k];
    int c0 = g_idx[i * KNN];
    float pcx = g_px[j] - g_px[c0];
    float pcy = g_py[j] - g_py[c0];
    float pcz = g_pz[j] - g_pz[c0];
    float vn  = sqrtf(pcx * pcx + pcy * pcy + pcz * pcz);
    sx[k] = pcx; sy[k] = pcy; sz[k] = pcz;
    rx[k] = pcx; ry[k] = pcy; rz[k] = pcz;
    sred[k] = (((ull)__float_as_uint(vn)) << 32) | (unsigned)(63 - k);
    __syncthreads();
    for (int off = 32; off > 0; off >>= 1) {
        if (k < off) {
            rx[k] += rx[k + off]; ry[k] += ry[k + off]; rz[k] += rz[k + off];
            ull o = sred[k + off];
            if (o > sred[k]) sred[k] = o;
        }
        __syncthreads();
    }
    int id1 = 63 - (int)(sred[0] & 0xFFFFFFFFu);
    float a1x = sx[id1], a1y = sy[id1], a1z = sz[id1];
    float n1 = sqrtf(a1x * a1x + a1y * a1y + a1z * a1z) + EPSF;
    a1x /= n1; a1y /= n1; a1z /= n1;
    float a2x = rx[0] * (1.0f / 64.0f), a2y = ry[0] * (1.0f / 64.0f), a2z = rz[0] * (1.0f / 64.0f);
    float n2 = sqrtf(a2x * a2x + a2y * a2y + a2z * a2z) + EPSF;
    a2x /= n2; a2y /= n2; a2z /= n2;
    float a3x = a1x + 1.5f * a2x, a3y = a1y + 1.5f * a2y, a3z = a1z + 1.5f * a2z;
    float n3 = sqrtf(a3x * a3x + a3y * a3y + a3z * a3z) + EPSF;
    a3x /= n3; a3y /= n3; a3z /= n3;

    float den = vn + EPSF;
    float f1 = (pcx * a1x + pcy * a1y + pcz * a1z) / den;
    float f2 = (pcx * a2x + pcy * a2y + pcz * a2z) / den;
    float f3 = (pcx * a3x + pcy * a3y + pcz * a3z) / den;
    *(float4*)(g_feat + (size_t)(i * KNN + k) * 4) = make_float4(f1, f2, f3, vn);
}

// ------------------ fused 5-layer MLP + max over K (2 points/block) ------------------
#define MLP_W_FLOATS 16640
#define MLP_SMEM ((MLP_W_FLOATS + 4 * 64 * 66) * 4)
__global__ void __launch_bounds__(256) mlp_kernel(const float* __restrict__ gw0,
                                                  const float* __restrict__ gw1,
                                                  const float* __restrict__ gw2,
                                                  const float* __restrict__ gw3,
                                                  const float* __restrict__ gw4) {
    extern __shared__ float smem[];
    float* w = smem;
    int tid = threadIdx.x;
    int half = tid >> 7, t128 = tid & 127;
    float* A = smem + MLP_W_FLOATS + half * (2 * 4224);
    float* B = A + 4224;
    int i = blockIdx.x * 2 + half;

    float4* wf = (float4*)w;
    for (int t = tid; t < 64; t += 256) wf[t] = ((const float4*)gw0)[t];
    {
        const float* gws[4] = {gw1, gw2, gw3, gw4};
        for (int l = 0; l < 4; l++)
            for (int t = tid; t < 1024; t += 256) wf[64 + l * 1024 + t] = ((const float4*)gws[l])[t];
    }
    for (int r = t128; r < 64; r += 128) {
        float4 f = *(const float4*)(g_feat + (size_t)(i * 64 + r) * 4);
        A[r * 66 + 0] = f.x; A[r * 66 + 1] = f.y; A[r * 66 + 2] = f.z; A[r * 66 + 3] = f.w;
    }
    __syncthreads();

    int r = t128 >> 1, h = t128 & 1;
    float* cur = A; float* nxt = B;
    const float* wl = w; int Kc = 4;
    for (int layer = 0; layer < 5; layer++) {
        ull acc[16];
#pragma unroll
        for (int q = 0; q < 16; q++) acc[q] = 0ULL;
        const float* wj = wl + h * 32;
        for (int c = 0; c < Kc; c++) {
            float xv = cur[r * 66 + c];
            ull xx = pack2(xv, xv);
            const ulonglong2* wrow = (const ulonglong2*)(wj + c * 64);
#pragma unroll
            for (int q4 = 0; q4 < 8; q4++) {
                ulonglong2 wv = wrow[q4];        // LDS.128 -> two FFMA2-ready pairs
                acc[q4 * 2]     = ffma2(xx, wv.x, acc[q4 * 2]);
                acc[q4 * 2 + 1] = ffma2(xx, wv.y, acc[q4 * 2 + 1]);
            }
        }
        float* orow = nxt + r * 66 + h * 32;
#pragma unroll
        for (int q = 0; q < 16; q++) {
            float vx, vy; unpack2(acc[q], vx, vy);
            float2 o; o.x = fmaxf(vx, 0.f); o.y = fmaxf(vy, 0.f);
            *(float2*)(orow + q * 2) = o;
        }
        __syncthreads();
        float* t = cur; cur = nxt; nxt = t;
        wl = w + 256 + layer * 4096; Kc = 64;
    }
    if (t128 < 64) {
        float m = cur[t128];
        for (int r2 = 1; r2 < 64; r2++) m = fmaxf(m, cur[r2 * 66 + t128]);
        g_emb[i * 64 + t128] = m;   // flat [n][64] view == conv input [64][8192]
    }
}

// ------------------ global axes reduce + fd ------------------
__global__ void __launch_bounds__(256) axes_reduce_kernel() {
    int t = blockIdx.x * blockDim.x + threadIdx.x;
    int lane = threadIdx.x & 31;
    unsigned b = __float_as_uint(g_vn[t]);
    ull pmx = (((ull)b) << 32) | (unsigned)(0xFFFFFFFFu - t);
    ull pmn = (((ull)b) << 32) | (unsigned)t;
#pragma unroll
    for (int off = 16; off > 0; off >>= 1) {
        ull ox = __shfl_down_sync(0xFFFFFFFFu, pmx, off);
        ull on = __shfl_down_sync(0xFFFFFFFFu, pmn, off);
        if (ox > pmx) pmx = ox;
        if (on < pmn) pmn = on;
    }
    if (lane == 0) { atomicMax(&g_gmax, pmx); atomicMin(&g_gmin, pmn); }
}

__global__ void fd_kernel() {
    int i = blockIdx.x * blockDim.x + threadIdx.x;
    if (i >= NP) return;
    int i1 = (int)(0xFFFFFFFFu - (unsigned)(g_gmax & 0xFFFFFFFFu));
    int i2 = (int)(g_gmin & 0xFFFFFFFFu);
    float n1 = g_vn[i1] + EPSF;
    float a1x = g_px[i1] / n1, a1y = g_py[i1] / n1, a1z = g_pz[i1] / n1;
    float n2 = g_vn[i2] + EPSF;
    float a2x = g_px[i2] / n2, a2y = g_py[i2] / n2, a2z = g_pz[i2] / n2;
    float a3x = a1x + 1.5f * a2x, a3y = a1y + 1.5f * a2y, a3z = a1z + 1.5f * a2z;
    float n3 = sqrtf(a3x * a3x + a3y * a3y + a3z * a3z) + EPSF;
    a3x /= n3; a3y /= n3; a3z /= n3;
    float x = g_px[i], y = g_py[i], z = g_pz[i], vn = g_vn[i];
    float den = vn + EPSF;
    float f1 = (x * a1x + y * a1y + z * a1z) / den;
    float f2 = (x * a2x + y * a2y + z * a2z) / den;
    float f3 = (x * a3x + y * a3y + z * a3z) / den;
    *(float4*)(g_fd + (size_t)i * 4) = make_float4(f1, f2, f3, vn);
}

// ------------------ GEMM with fused input-BN+ReLU -------------------------------
// Y[M][8192] = W[M][Kc] @ relu(bn(X))[Kc][8192] + bias; xsc==null -> raw X
__global__ void __launch_bounds__(256) gemm_kernel(const float* __restrict__ W,
                                                   const float* __restrict__ X,
                                                   const float* __restrict__ bias,
                                                   float* __restrict__ Y,
                                                   int Kc,
                                                   const float* __restrict__ xsc,
                                                   const float* __restrict__ xsh) {
    __shared__ float sW[16][68];
    __shared__ float sX[16][132];
    int tid = threadIdx.x;
    int bm = blockIdx.y * 64, bn = blockIdx.x * 128;
    int tx = tid & 15, ty = tid >> 4;
    ull acc[4][4];
#pragma unroll
    for (int u = 0; u < 4; u++)
#pragma unroll
        for (int q = 0; q < 4; q++) acc[u][q] = 0ULL;

    for (int k0 = 0; k0 < Kc; k0 += 16) {
        for (int t = tid; t < 1024; t += 256) {
            int kk = t & 15, m = t >> 4;
            float val = 0.f;
            if (k0 + kk < Kc) val = W[(size_t)(bm + m) * Kc + k0 + kk];
            sW[kk][m] = val;
        }
        for (int t = tid; t < 2048; t += 256) {
            int n = t & 127, kk = t >> 7;
            float val = 0.f;
            if (k0 + kk < Kc) {
                val = X[(size_t)(k0 + kk) * NP + bn + n];
                if (xsc) val = fmaxf(val * xsc[k0 + kk] + xsh[k0 + kk], 0.f);
            }
            sX[kk][n] = val;
        }
        __syncthreads();
#pragma unroll
        for (int kk = 0; kk < 16; kk++) {
            float4 a = *(const float4*)&sW[kk][ty * 4];
            const ulonglong2* bx = (const ulonglong2*)&sX[kk][tx * 8];
            ulonglong2 b01 = bx[0];
            ulonglong2 b23 = bx[1];
            float av[4] = {a.x, a.y, a.z, a.w};
#pragma unroll
            for (int u = 0; u < 4; u++) {
                ull aa = pack2(av[u], av[u]);
                acc[u][0] = ffma2(aa, b01.x, acc[u][0]);
                acc[u][1] = ffma2(aa, b01.y, acc[u][1]);
                acc[u][2] = ffma2(aa, b23.x, acc[u][2]);
                acc[u][3] = ffma2(aa, b23.y, acc[u][3]);
            }
        }
        __syncthreads();
    }
    int m0 = bm + ty * 4;
#pragma unroll
    for (int u = 0; u < 4; u++) {
        float bv = bias[m0 + u];
        float o[8];
#pragma unroll
        for (int q = 0; q < 4; q++) {
            float vx, vy; unpack2(acc[u][q], vx, vy);
            o[q * 2] = vx + bv; o[q * 2 + 1] = vy + bv;
        }
        float* yrow = Y + (size_t)(m0 + u) * NP + bn + tx * 8;
        *(float4*)yrow       = make_float4(o[0], o[1], o[2], o[3]);
        *(float4*)(yrow + 4) = make_float4(o[4], o[5], o[6], o[7]);
    }
}

// ------------------ BatchNorm stats (one pass) ------------------
__global__ void __launch_bounds__(256) bn_stats_kernel(const float* __restrict__ Y,
                                                       const float* __restrict__ gamma,
                                                       const float* __restrict__ beta,
                                                       float* __restrict__ sc,
                                                       float* __restrict__ sh) {
    int ch = blockIdx.x, tid = threadIdx.x;
    const float4* row = (const float4*)(Y + (size_t)ch * NP);
    float s = 0.f, s2 = 0.f;
    for (int t = tid; t < NP / 4; t += 256) {
        float4 v = row[t];
        s  += v.x + v.y + v.z + v.w;
        s2 += v.x * v.x + v.y * v.y + v.z * v.z + v.w * v.w;
    }
    __shared__ float r1[256], r2[256];
    r1[tid] = s; r2[tid] = s2; __syncthreads();
    for (int off = 128; off > 0; off >>= 1) {
        if (tid < off) { r1[tid] += r1[tid + off]; r2[tid] += r2[tid + off]; }
        __syncthreads();
    }
    if (tid == 0) {
        float mu = r1[0] * (1.0f / NP);
        float var = r2[0] * (1.0f / NP) - mu * mu;
        var = fmaxf(var, 0.f);
        float s0 = gamma[ch] * rsqrtf(var + 1e-5f);
        sc[ch] = s0;
        sh[ch] = beta[ch] - mu * s0;
    }
}

__global__ void bn_apply_kernel(const float4* __restrict__ Yin, float4* __restrict__ Yout,
                                const float* __restrict__ sc, const float* __restrict__ sh) {
    int idx = blockIdx.x * blockDim.x + threadIdx.x;  // over 1024*NP/4
    int ch = idx >> 11;                               // NP/4 = 2048 per channel
    float s0 = sc[ch], s1 = sh[ch];
    float4 v = Yin[idx];
    v.x = fmaxf(v.x * s0 + s1, 0.f);
    v.y = fmaxf(v.y * s0 + s1, 0.f);
    v.z = fmaxf(v.z * s0 + s1, 0.f);
    v.w = fmaxf(v.w * s0 + s1, 0.f);
    Yout[idx] = v;
}

// ------------------------- launch -------------------------
extern "C" void kernel_launch(void* const* d_in, const int* in_sizes, int n_in,
                              void* d_out, int out_size) {
    const float* pts  = (const float*)d_in[0];
    const float* gw0  = (const float*)d_in[1];
    const float* gw1  = (const float*)d_in[2];
    const float* gw2  = (const float*)d_in[3];
    const float* gw3  = (const float*)d_in[4];
    const float* gw4  = (const float*)d_in[5];
    const float* c1w  = (const float*)d_in[6];
    const float* c1b  = (const float*)d_in[7];
    const float* bn1g = (const float*)d_in[8];
    const float* bn1b = (const float*)d_in[9];
    const float* c2w  = (const float*)d_in[10];
    const float* c2b  = (const float*)d_in[11];
    const float* bn2g = (const float*)d_in[12];
    const float* bn2b = (const float*)d_in[13];
    const float* c3w  = (const float*)d_in[14];
    const float* c3b  = (const float*)d_in[15];
    const float* bn3g = (const float*)d_in[16];
    const float* bn3b = (const float*)d_in[17];
    const float* c4w  = (const float*)d_in[18];
    const float* c4b  = (const float*)d_in[19];
    const float* bn4g = (const float*)d_in[20];
    const float* bn4b = (const float*)d_in[21];
    float* out = (float*)d_out;

    float *p_fd, *p_emb, *p_y1, *p_y3, *p_y4;
    float *p_sc1, *p_sh1, *p_sc2, *p_sh2, *p_sc3, *p_sh3, *p_sc4, *p_sh4;
    cudaGetSymbolAddress((void**)&p_fd,  g_fd);
    cudaGetSymbolAddress((void**)&p_emb, g_emb);
    cudaGetSymbolAddress((void**)&p_y1,  g_y1);
    cudaGetSymbolAddress((void**)&p_y3,  g_y3);
    cudaGetSymbolAddress((void**)&p_y4,  g_y4);
    cudaGetSymbolAddress((void**)&p_sc1, g_sc1);
    cudaGetSymbolAddress((void**)&p_sh1, g_sh1);
    cudaGetSymbolAddress((void**)&p_sc2, g_sc2);
    cudaGetSymbolAddress((void**)&p_sh2, g_sh2);
    cudaGetSymbolAddress((void**)&p_sc3, g_sc3);
    cudaGetSymbolAddress((void**)&p_sh3, g_sh3);
    cudaGetSymbolAddress((void**)&p_sc4, g_sc4);
    cudaGetSymbolAddress((void**)&p_sh4, g_sh4);

    cudaFuncSetAttribute(mlp_kernel, cudaFuncAttributeMaxDynamicSharedMemorySize, MLP_SMEM);

    prep_kernel<<<(NP + 255) / 256, 256>>>(pts);                 // 1
    knn_kernel<<<NP, 256>>>();                                   // 2
    featknn_kernel<<<NP, 64>>>();                                // 3
    mlp_kernel<<<NP / 2, 256, MLP_SMEM>>>(gw0, gw1, gw2, gw3, gw4); // 4 (ncu captures this)
    axes_reduce_kernel<<<NP / 256, 256>>>();                     // 5
    fd_kernel<<<(NP + 255) / 256, 256>>>();                      // 6

    // conv1 (64 <- 4), raw input
    gemm_kernel<<<dim3(NP / 128, 1), 256>>>(c1w, p_fd, c1b, p_y1, 4, nullptr, nullptr);
    bn_stats_kernel<<<64, 256>>>(p_y1, bn1g, bn1b, p_sc1, p_sh1);
    // conv2 (128 <- 64), input = relu(bn1(y1)); write raw into concat rows 64..191
    gemm_kernel<<<dim3(NP / 128, 2), 256>>>(c2w, p_y1, c2b, p_emb + 64 * NP, 64, p_sc1, p_sh1);
    bn_stats_kernel<<<128, 256>>>(p_emb + 64 * NP, bn2g, bn2b, p_sc2 + 64, p_sh2 + 64);
    // conv3 (256 <- 192), input = emb with per-channel affine (identity for 0..63)
    gemm_kernel<<<dim3(NP / 128, 4), 256>>>(c3w, p_emb, c3b, p_y3, 192, p_sc2, p_sh2);
    bn_stats_kernel<<<256, 256>>>(p_y3, bn3g, bn3b, p_sc3, p_sh3);
    // conv4 (1024 <- 256), input = relu(bn3(y3))
    gemm_kernel<<<dim3(NP / 128, 16), 256>>>(c4w, p_y3, c4b, p_y4, 256, p_sc3, p_sh3);
    bn_stats_kernel<<<1024, 256>>>(p_y4, bn4g, bn4b, p_sc4, p_sh4);
    bn_apply_kernel<<<1024 * NP / 1024, 256>>>((const float4*)p_y4, (float4*)out, p_sc4, p_sh4);

    (void)in_sizes; (void)n_in; (void)out_size;
}

// round 6
// speedup vs baseline: 1.1546x; 1.1546x over previous
#include <cuda_runtime.h>
#include <stdint.h>

#define NP   8192
#define KNN  64
#define EPSF 1e-7f
typedef unsigned long long ull;

// ------------------------- static scratch -------------------------
__device__ float g_px[NP], g_py[NP], g_pz[NP], g_vn[NP];
__device__ __align__(16) float4 g_pt4[NP];
__device__ ull   g_gmax, g_gmin;
__device__ int   g_idx[NP * KNN];
__device__ __align__(16) float g_feat[NP * KNN * 4];
__device__ __align__(16) float g_fd[NP * 4];
__device__ __align__(16) float g_emb[192 * NP];
__device__ __align__(16) float g_y1[64 * NP];
__device__ __align__(16) float g_y3[256 * NP];
__device__ __align__(16) float g_y4[1024 * NP];
__device__ float g_sc1[64],  g_sh1[64];
__device__ float g_sc2[192], g_sh2[192];
__device__ float g_sc3[256], g_sh3[256];
__device__ float g_sc4[1024], g_sh4[1024];

// ------------------------- f32x2 helpers -------------------------
__device__ __forceinline__ ull ffma2(ull a, ull b, ull c) {
    ull d;
    asm("fma.rn.f32x2 %0, %1, %2, %3;" : "=l"(d) : "l"(a), "l"(b), "l"(c));
    return d;
}
__device__ __forceinline__ ull pack2(float x, float y) {
    ull d;
    asm("mov.b64 %0, {%1, %2};" : "=l"(d) : "f"(x), "f"(y));
    return d;
}
__device__ __forceinline__ void unpack2(ull v, float& x, float& y) {
    asm("mov.b64 {%0, %1}, %2;" : "=f"(x), "=f"(y) : "l"(v));
}

// ------------------------- prep -------------------------
__global__ void prep_kernel(const float* __restrict__ pts) {
    int i = blockIdx.x * blockDim.x + threadIdx.x;
    if (i == 0) { g_gmax = 0ULL; g_gmin = ~0ULL; }
    if (i < 64) { g_sc2[i] = 1.0f; g_sh2[i] = 0.0f; }   // identity BN for emb_up rows
    if (i < NP) {
        float x = pts[3 * i], y = pts[3 * i + 1], z = pts[3 * i + 2];
        g_px[i] = x; g_py[i] = y; g_pz[i] = z;
        float rr = x * x + y * y + z * z;
        g_vn[i] = sqrtf(rr);
        g_pt4[i] = make_float4(x, y, z, rr);
    }
}

// ------------------------- KNN rank-64 selection (deterministic) -------------------------
__global__ void __launch_bounds__(256) knn_kernel() {
    const int i = blockIdx.x, tid = threadIdx.x;
    const int lane = tid & 31, warp = tid >> 5;
    __shared__ int wsum[16];
    __shared__ int wcntL[8], wcntE[8];
    __shared__ ull cmin;
    __shared__ int nact;
    __shared__ int eqbuf[256];
    __shared__ unsigned short actkey[2048];

    float4 q4 = g_pt4[i];
    unsigned key[32];
#pragma unroll
    for (int s = 0; s < 32; s++) {
        float4 p = g_pt4[s * 256 + tid];
        float d = q4.w - 2.0f * (q4.x * p.x + q4.y * p.y + q4.z * p.z) + p.w;
        unsigned u = __float_as_uint(d);
        key[s] = u ^ ((u & 0x80000000u) ? 0xFFFFFFFFu : 0x80000000u);
    }
    if (tid == 0) { cmin = ~0ULL; nact = 0; }
    __syncthreads();

    {
        ull lm = ~0ULL;
#pragma unroll
        for (int s = 0; s < 32; s++) {
            ull pk = (((ull)key[s]) << 32) | (unsigned)(s * 256 + tid);
            lm = (pk < lm) ? pk : lm;
        }
        atomicMin(&cmin, lm);
    }

    unsigned v = 0u;
    int cless = 0;
    for (int b = 31; b >= 16; b--) {
        unsigned cand = v | (1u << b);
        int cnt = 0;
#pragma unroll
        for (int s = 0; s < 32; s++) cnt += (key[s] < cand) ? 1 : 0;
        cnt = __reduce_add_sync(0xFFFFFFFFu, cnt);
        int bank = (b & 1) << 3;
        if (lane == 0) wsum[bank + warp] = cnt;
        __syncthreads();
        int tot = 0;
#pragma unroll
        for (int w = 0; w < 8; w++) tot += wsum[bank + w];
        if (tot < KNN) { v = cand; cless = tot; }
    }

    unsigned p16 = v >> 16;
#pragma unroll
    for (int s = 0; s < 32; s++) {
        if ((key[s] >> 16) == p16) {
            int a = atomicAdd(&nact, 1);
            if (a < 2048) actkey[a] = (unsigned short)(key[s] & 0xFFFFu);
        }
    }
    __syncthreads();
    int na = nact;
    int base = cless;

    if (na <= 2048) {
        for (int b = 15; b >= 0; b--) {
            unsigned cl = (v | (1u << b)) & 0xFFFFu;
            int cnt = 0;
            for (int t = tid; t < na; t += 256) cnt += (actkey[t] < cl) ? 1 : 0;
            cnt = __reduce_add_sync(0xFFFFFFFFu, cnt);
            int bank = (b & 1) << 3;
            if (lane == 0) wsum[bank + warp] = cnt;
            __syncthreads();
            int tot = base;
#pragma unroll
            for (int w = 0; w < 8; w++) tot += wsum[bank + w];
            if (tot < KNN) { v |= (1u << b); cless = tot; }
        }
    } else {
        for (int b = 15; b >= 0; b--) {
            unsigned cand = v | (1u << b);
            int cnt = 0;
#pragma unroll
            for (int s = 0; s < 32; s++) cnt += (key[s] < cand) ? 1 : 0;
            cnt = __reduce_add_sync(0xFFFFFFFFu, cnt);
            int bank = (b & 1) << 3;
            if (lane == 0) wsum[bank + warp] = cnt;
            __syncthreads();
            int tot = 0;
#pragma unroll
            for (int w = 0; w < 8; w++) tot += wsum[bank + w];
            if (tot < KNN) { v = cand; cless = tot; }
        }
    }

    int center = (int)(cmin & 0xFFFFFFFFu);
    unsigned ckey = (unsigned)(cmin >> 32);
    int startEq = (ckey == v) ? (cless + 1) : cless;

    {
        int cl2 = 0, ce2 = 0;
#pragma unroll
        for (int s = 0; s < 32; s++) {
            int n = s * 256 + tid;
            unsigned kk = key[s];
            cl2 += (kk < v && n != center) ? 1 : 0;
            ce2 += (kk == v && n != center) ? 1 : 0;
        }
        cl2 = __reduce_add_sync(0xFFFFFFFFu, cl2);
        ce2 = __reduce_add_sync(0xFFFFFFFFu, ce2);
        if (lane == 0) { wcntL[warp] = cl2; wcntE[warp] = ce2; }
        __syncthreads();
        int offL = 0, offE = 0;
        for (int w = 0; w < warp; w++) { offL += wcntL[w]; offE += wcntE[w]; }
        unsigned lt = (1u << lane) - 1u;
#pragma unroll
        for (int s = 0; s < 32; s++) {
            int n = s * 256 + tid;
            unsigned kk = key[s];
            bool pl = (kk < v) && (n != center);
            bool pe = (kk == v) && (n != center);
            unsigned ml = __ballot_sync(0xFFFFFFFFu, pl);
            unsigned me = __ballot_sync(0xFFFFFFFFu, pe);
            if (pl) g_idx[i * KNN + 1 + offL + __popc(ml & lt)] = n;
            if (pe) { int p = offE + __popc(me & lt); if (p < 256) eqbuf[p] = n; }
            offL += __popc(ml); offE += __popc(me);
        }
    }
    __syncthreads();
    if (tid == 0) {
        g_idx[i * KNN] = center;
        int neq = 0;
        for (int w = 0; w < 8; w++) neq += wcntE[w];
        int q = KNN - startEq;
        int m = neq; if (m > 256) m = 256;
        for (int a = 0; a < q; a++) {
            int bi = a;
            for (int bj = a + 1; bj < m; bj++)
                if (eqbuf[bj] < eqbuf[bi]) bi = bj;
            int t = eqbuf[a]; eqbuf[a] = eqbuf[bi]; eqbuf[bi] = t;
            g_idx[i * KNN + startEq + a] = eqbuf[a];
        }
    }
}

// ------------------ per-query rotation-invariant KNN features ------------------
__global__ void __launch_bounds__(64) featknn_kernel() {
    int i = blockIdx.x, k = threadIdx.x;
    __shared__ float sx[64], sy[64], sz[64];
    __shared__ ull sred[64];
    __shared__ float rx[64], ry[64], rz[64];

    int j  = g_idx[i * KNN + k];
    int c0 = g_idx[i * KNN];
    float pcx = g_px[j] - g_px[c0];
    float pcy = g_py[j] - g_py[c0];
    float pcz = g_pz[j] - g_pz[c0];
    float vn  = sqrtf(pcx * pcx + pcy * pcy + pcz * pcz);
    sx[k] = pcx; sy[k] = pcy; sz[k] = pcz;
    rx[k] = pcx; ry[k] = pcy; rz[k] = pcz;
    sred[k] = (((ull)__float_as_uint(vn)) << 32) | (unsigned)(63 - k);
    __syncthreads();
    for (int off = 32; off > 0; off >>= 1) {
        if (k < off) {
            rx[k] += rx[k + off]; ry[k] += ry[k + off]; rz[k] += rz[k + off];
            ull o = sred[k + off];
            if (o > sred[k]) sred[k] = o;
        }
        __syncthreads();
    }
    int id1 = 63 - (int)(sred[0] & 0xFFFFFFFFu);
    float a1x = sx[id1], a1y = sy[id1], a1z = sz[id1];
    float n1 = sqrtf(a1x * a1x + a1y * a1y + a1z * a1z) + EPSF;
    a1x /= n1; a1y /= n1; a1z /= n1;
    float a2x = rx[0] * (1.0f / 64.0f), a2y = ry[0] * (1.0f / 64.0f), a2z = rz[0] * (1.0f / 64.0f);
    float n2 = sqrtf(a2x * a2x + a2y * a2y + a2z * a2z) + EPSF;
    a2x /= n2; a2y /= n2; a2z /= n2;
    float a3x = a1x + 1.5f * a2x, a3y = a1y + 1.5f * a2y, a3z = a1z + 1.5f * a2z;
    float n3 = sqrtf(a3x * a3x + a3y * a3y + a3z * a3z) + EPSF;
    a3x /= n3; a3y /= n3; a3z /= n3;

    float den = vn + EPSF;
    float f1 = (pcx * a1x + pcy * a1y + pcz * a1z) / den;
    float f2 = (pcx * a2x + pcy * a2y + pcz * a2z) / den;
    float f3 = (pcx * a3x + pcy * a3y + pcz * a3z) / den;
    *(float4*)(g_feat + (size_t)(i * KNN + k) * 4) = make_float4(f1, f2, f3, vn);
}

// ------------------ global axes reduce + fd ------------------
__global__ void __launch_bounds__(256) axes_reduce_kernel() {
    int t = blockIdx.x * blockDim.x + threadIdx.x;
    int lane = threadIdx.x & 31;
    unsigned b = __float_as_uint(g_vn[t]);
    ull pmx = (((ull)b) << 32) | (unsigned)(0xFFFFFFFFu - t);
    ull pmn = (((ull)b) << 32) | (unsigned)t;
#pragma unroll
    for (int off = 16; off > 0; off >>= 1) {
        ull ox = __shfl_down_sync(0xFFFFFFFFu, pmx, off);
        ull on = __shfl_down_sync(0xFFFFFFFFu, pmn, off);
        if (ox > pmx) pmx = ox;
        if (on < pmn) pmn = on;
    }
    if (lane == 0) { atomicMax(&g_gmax, pmx); atomicMin(&g_gmin, pmn); }
}

__global__ void fd_kernel() {
    int i = blockIdx.x * blockDim.x + threadIdx.x;
    if (i >= NP) return;
    int i1 = (int)(0xFFFFFFFFu - (unsigned)(g_gmax & 0xFFFFFFFFu));
    int i2 = (int)(g_gmin & 0xFFFFFFFFu);
    float n1 = g_vn[i1] + EPSF;
    float a1x = g_px[i1] / n1, a1y = g_py[i1] / n1, a1z = g_pz[i1] / n1;
    float n2 = g_vn[i2] + EPSF;
    float a2x = g_px[i2] / n2, a2y = g_py[i2] / n2, a2z = g_pz[i2] / n2;
    float a3x = a1x + 1.5f * a2x, a3y = a1y + 1.5f * a2y, a3z = a1z + 1.5f * a2z;
    float n3 = sqrtf(a3x * a3x + a3y * a3y + a3z * a3z) + EPSF;
    a3x /= n3; a3y /= n3; a3z /= n3;
    float x = g_px[i], y = g_py[i], z = g_pz[i], vn = g_vn[i];
    float den = vn + EPSF;
    float f1 = (x * a1x + y * a1y + z * a1z) / den;
    float f2 = (x * a2x + y * a2y + z * a2z) / den;
    float f3 = (x * a3x + y * a3y + z * a3z) / den;
    *(float4*)(g_fd + (size_t)i * 4) = make_float4(f1, f2, f3, vn);
}

// ------------------ fused 5-layer MLP, register-tiled outer product ------------------
// 2 points/block, 128 thr/point, thread tile = 4 rows x 8 cols.
// Activations transposed in smem: A^T[col][68]; only live layer's weights staged.
#define AST 68                          // activation/weight row stride (floats)
#define WBUF (64 * AST)                 // 4352 floats
#define MLP_SMEM ((WBUF * 5) * 4)       // W + 2 pts * 2 bufs = 87,040 B
__global__ void __launch_bounds__(256) mlp_kernel(const float* __restrict__ gw0,
                                                  const float* __restrict__ gw1,
                                                  const float* __restrict__ gw2,
                                                  const float* __restrict__ gw3,
                                                  const float* __restrict__ gw4) {
    extern __shared__ float smem[];
    float* W = smem;                                    // [64][AST]
    int tid = threadIdx.x;
    int half = tid >> 7, t128 = tid & 127;
    float* A = smem + WBUF + half * 2 * WBUF;
    float* B = A + WBUF;
    int i = blockIdx.x * 2 + half;

    // init A^T (cols 0..3) from g_feat
    if (t128 < 64) {
        int r = t128;
        float4 f = *(const float4*)(g_feat + (size_t)(i * 64 + r) * 4);
        A[0 * AST + r] = f.x; A[1 * AST + r] = f.y;
        A[2 * AST + r] = f.z; A[3 * AST + r] = f.w;
    }

    int tx = t128 & 7, ty = t128 >> 3;                  // col-group, row-group
    float* cur = A; float* nxt = B;
#pragma unroll
    for (int layer = 0; layer < 5; layer++) {
        const int Kc = (layer == 0) ? 4 : 64;
        const float* gw = (layer == 0) ? gw0 : (layer == 1) ? gw1 :
                          (layer == 2) ? gw2 : (layer == 3) ? gw3 : gw4;
        __syncthreads();                                // W free, prev nxt stores visible
        for (int t = tid; t < Kc * 64; t += 256) W[(t >> 6) * AST + (t & 63)] = gw[t];
        __syncthreads();

        ull acc[4][4];
#pragma unroll
        for (int u = 0; u < 4; u++)
#pragma unroll
            for (int q = 0; q < 4; q++) acc[u][q] = 0ULL;

        for (int k = 0; k < Kc; k++) {
            float4 a = *(const float4*)&cur[k * AST + ty * 4];
            const ulonglong2* bp = (const ulonglong2*)&W[k * AST + tx * 8];
            ulonglong2 b01 = bp[0], b23 = bp[1];
            ull d0 = pack2(a.x, a.x), d1 = pack2(a.y, a.y);
            ull d2 = pack2(a.z, a.z), d3 = pack2(a.w, a.w);
            acc[0][0] = ffma2(d0, b01.x, acc[0][0]); acc[0][1] = ffma2(d0, b01.y, acc[0][1]);
            acc[0][2] = ffma2(d0, b23.x, acc[0][2]); acc[0][3] = ffma2(d0, b23.y, acc[0][3]);
            acc[1][0] = ffma2(d1, b01.x, acc[1][0]); acc[1][1] = ffma2(d1, b01.y, acc[1][1]);
            acc[1][2] = ffma2(d1, b23.x, acc[1][2]); acc[1][3] = ffma2(d1, b23.y, acc[1][3]);
            acc[2][0] = ffma2(d2, b01.x, acc[2][0]); acc[2][1] = ffma2(d2, b01.y, acc[2][1]);
            acc[2][2] = ffma2(d2, b23.x, acc[2][2]); acc[2][3] = ffma2(d2, b23.y, acc[2][3]);
            acc[3][0] = ffma2(d3, b01.x, acc[3][0]); acc[3][1] = ffma2(d3, b01.y, acc[3][1]);
            acc[3][2] = ffma2(d3, b23.x, acc[3][2]); acc[3][3] = ffma2(d3, b23.y, acc[3][3]);
        }
        // store transposed with relu: cols tx*8+2j(+1), rows ty*4..ty*4+3
#pragma unroll
        for (int jq = 0; jq < 4; jq++) {
            float x0, y0, x1, y1, x2, y2, x3, y3;
            unpack2(acc[0][jq], x0, y0); unpack2(acc[1][jq], x1, y1);
            unpack2(acc[2][jq], x2, y2); unpack2(acc[3][jq], x3, y3);
            int c = tx * 8 + jq * 2;
            *(float4*)&nxt[c * AST + ty * 4] =
                make_float4(fmaxf(x0, 0.f), fmaxf(x1, 0.f), fmaxf(x2, 0.f), fmaxf(x3, 0.f));
            *(float4*)&nxt[(c + 1) * AST + ty * 4] =
                make_float4(fmaxf(y0, 0.f), fmaxf(y1, 0.f), fmaxf(y2, 0.f), fmaxf(y3, 0.f));
        }
        float* t = cur; cur = nxt; nxt = t;
    }
    __syncthreads();
    if (t128 < 64) {
        float m = 0.f;                                  // post-relu values are >= 0
        const float4* col = (const float4*)&cur[t128 * AST];
#pragma unroll
        for (int q = 0; q < 16; q++) {
            float4 v = col[q];
            m = fmaxf(m, fmaxf(fmaxf(v.x, v.y), fmaxf(v.z, v.w)));
        }
        g_emb[i * 64 + t128] = m;                       // flat [n][64] == conv view [64][8192]
    }
}

// ------------------ GEMM with fused input-BN+ReLU (sc/sh staged in smem) --------
__global__ void __launch_bounds__(256) gemm_kernel(const float* __restrict__ W,
                                                   const float* __restrict__ X,
                                                   const float* __restrict__ bias,
                                                   float* __restrict__ Y,
                                                   int Kc,
                                                   const float* __restrict__ xsc,
                                                   const float* __restrict__ xsh) {
    __shared__ float sW[16][68];
    __shared__ float sX[16][132];
    __shared__ float ssc[256], ssh[256];
    int tid = threadIdx.x;
    int bm = blockIdx.y * 64, bn = blockIdx.x * 128;
    int tx = tid & 15, ty = tid >> 4;
    if (xsc) {
        for (int t = tid; t < Kc; t += 256) { ssc[t] = xsc[t]; ssh[t] = xsh[t]; }
    }
    ull acc[4][4];
#pragma unroll
    for (int u = 0; u < 4; u++)
#pragma unroll
        for (int q = 0; q < 4; q++) acc[u][q] = 0ULL;
    __syncthreads();

    for (int k0 = 0; k0 < Kc; k0 += 16) {
        for (int t = tid; t < 1024; t += 256) {
            int kk = t & 15, m = t >> 4;
            float val = 0.f;
            if (k0 + kk < Kc) val = W[(size_t)(bm + m) * Kc + k0 + kk];
            sW[kk][m] = val;
        }
        for (int t = tid; t < 2048; t += 256) {
            int n = t & 127, kk = t >> 7;
            float val = 0.f;
            if (k0 + kk < Kc) {
                val = X[(size_t)(k0 + kk) * NP + bn + n];
                if (xsc) val = fmaxf(val * ssc[k0 + kk] + ssh[k0 + kk], 0.f);
            }
            sX[kk][n] = val;
        }
        __syncthreads();
#pragma unroll
        for (int kk = 0; kk < 16; kk++) {
            float4 a = *(const float4*)&sW[kk][ty * 4];
            const ulonglong2* bx = (const ulonglong2*)&sX[kk][tx * 8];
            ulonglong2 b01 = bx[0];
            ulonglong2 b23 = bx[1];
            float av[4] = {a.x, a.y, a.z, a.w};
#pragma unroll
            for (int u = 0; u < 4; u++) {
                ull aa = pack2(av[u], av[u]);
                acc[u][0] = ffma2(aa, b01.x, acc[u][0]);
                acc[u][1] = ffma2(aa, b01.y, acc[u][1]);
                acc[u][2] = ffma2(aa, b23.x, acc[u][2]);
                acc[u][3] = ffma2(aa, b23.y, acc[u][3]);
            }
        }
        __syncthreads();
    }
    int m0 = bm + ty * 4;
#pragma unroll
    for (int u = 0; u < 4; u++) {
        float bv = bias[m0 + u];
        float o[8];
#pragma unroll
        for (int q = 0; q < 4; q++) {
            float vx, vy; unpack2(acc[u][q], vx, vy);
            o[q * 2] = vx + bv; o[q * 2 + 1] = vy + bv;
        }
        float* yrow = Y + (size_t)(m0 + u) * NP + bn + tx * 8;
        *(float4*)yrow       = make_float4(o[0], o[1], o[2], o[3]);
        *(float4*)(yrow + 4) = make_float4(o[4], o[5], o[6], o[7]);
    }
}

// ------------------ BatchNorm stats (one pass) ------------------
__global__ void __launch_bounds__(256) bn_stats_kernel(const float* __restrict__ Y,
                                                       const float* __restrict__ gamma,
                                                       const float* __restrict__ beta,
                                                       float* __restrict__ sc,
                                                       float* __restrict__ sh) {
    int ch = blockIdx.x, tid = threadIdx.x;
    const float4* row = (const float4*)(Y + (size_t)ch * NP);
    float s = 0.f, s2 = 0.f;
    for (int t = tid; t < NP / 4; t += 256) {
        float4 v = row[t];
        s  += v.x + v.y + v.z + v.w;
        s2 += v.x * v.x + v.y * v.y + v.z * v.z + v.w * v.w;
    }
    __shared__ float r1[256], r2[256];
    r1[tid] = s; r2[tid] = s2; __syncthreads();
    for (int off = 128; off > 0; off >>= 1) {
        if (tid < off) { r1[tid] += r1[tid + off]; r2[tid] += r2[tid + off]; }
        __syncthreads();
    }
    if (tid == 0) {
        float mu = r1[0] * (1.0f / NP);
        float var = r2[0] * (1.0f / NP) - mu * mu;
        var = fmaxf(var, 0.f);
        float s0 = gamma[ch] * rsqrtf(var + 1e-5f);
        sc[ch] = s0;
        sh[ch] = beta[ch] - mu * s0;
    }
}

__global__ void bn_apply_kernel(const float4* __restrict__ Yin, float4* __restrict__ Yout,
                                const float* __restrict__ sc, const float* __restrict__ sh) {
    int idx = blockIdx.x * blockDim.x + threadIdx.x;
    int ch = idx >> 11;
    float s0 = sc[ch], s1 = sh[ch];
    float4 v = Yin[idx];
    v.x = fmaxf(v.x * s0 + s1, 0.f);
    v.y = fmaxf(v.y * s0 + s1, 0.f);
    v.z = fmaxf(v.z * s0 + s1, 0.f);
    v.w = fmaxf(v.w * s0 + s1, 0.f);
    Yout[idx] = v;
}

// ------------------------- launch -------------------------
extern "C" void kernel_launch(void* const* d_in, const int* in_sizes, int n_in,
                              void* d_out, int out_size) {
    const float* pts  = (const float*)d_in[0];
    const float* gw0  = (const float*)d_in[1];
    const float* gw1  = (const float*)d_in[2];
    const float* gw2  = (const float*)d_in[3];
    const float* gw3  = (const float*)d_in[4];
    const float* gw4  = (const float*)d_in[5];
    const float* c1w  = (const float*)d_in[6];
    const float* c1b  = (const float*)d_in[7];
    const float* bn1g = (const float*)d_in[8];
    const float* bn1b = (const float*)d_in[9];
    const float* c2w  = (const float*)d_in[10];
    const float* c2b  = (const float*)d_in[11];
    const float* bn2g = (const float*)d_in[12];
    const float* bn2b = (const float*)d_in[13];
    const float* c3w  = (const float*)d_in[14];
    const float* c3b  = (const float*)d_in[15];
    const float* bn3g = (const float*)d_in[16];
    const float* bn3b = (const float*)d_in[17];
    const float* c4w  = (const float*)d_in[18];
    const float* c4b  = (const float*)d_in[19];
    const float* bn4g = (const float*)d_in[20];
    const float* bn4b = (const float*)d_in[21];
    float* out = (float*)d_out;

    float *p_fd, *p_emb, *p_y1, *p_y3, *p_y4;
    float *p_sc1, *p_sh1, *p_sc2, *p_sh2, *p_sc3, *p_sh3, *p_sc4, *p_sh4;
    cudaGetSymbolAddress((void**)&p_fd,  g_fd);
    cudaGetSymbolAddress((void**)&p_emb, g_emb);
    cudaGetSymbolAddress((void**)&p_y1,  g_y1);
    cudaGetSymbolAddress((void**)&p_y3,  g_y3);
    cudaGetSymbolAddress((void**)&p_y4,  g_y4);
    cudaGetSymbolAddress((void**)&p_sc1, g_sc1);
    cudaGetSymbolAddress((void**)&p_sh1, g_sh1);
    cudaGetSymbolAddress((void**)&p_sc2, g_sc2);
    cudaGetSymbolAddress((void**)&p_sh2, g_sh2);
    cudaGetSymbolAddress((void**)&p_sc3, g_sc3);
    cudaGetSymbolAddress((void**)&p_sh3, g_sh3);
    cudaGetSymbolAddress((void**)&p_sc4, g_sc4);
    cudaGetSymbolAddress((void**)&p_sh4, g_sh4);

    cudaFuncSetAttribute(mlp_kernel, cudaFuncAttributeMaxDynamicSharedMemorySize, MLP_SMEM);

    prep_kernel<<<(NP + 255) / 256, 256>>>(pts);                 // 1
    axes_reduce_kernel<<<NP / 256, 256>>>();                     // 2
    fd_kernel<<<(NP + 255) / 256, 256>>>();                      // 3
    knn_kernel<<<NP, 256>>>();                                   // 4  (ncu captures this)
    featknn_kernel<<<NP, 64>>>();                                // 5
    mlp_kernel<<<NP / 2, 256, MLP_SMEM>>>(gw0, gw1, gw2, gw3, gw4); // 6

    gemm_kernel<<<dim3(NP / 128, 1), 256>>>(c1w, p_fd, c1b, p_y1, 4, nullptr, nullptr);
    bn_stats_kernel<<<64, 256>>>(p_y1, bn1g, bn1b, p_sc1, p_sh1);
    gemm_kernel<<<dim3(NP / 128, 2), 256>>>(c2w, p_y1, c2b, p_emb + 64 * NP, 64, p_sc1, p_sh1);
    bn_stats_kernel<<<128, 256>>>(p_emb + 64 * NP, bn2g, bn2b, p_sc2 + 64, p_sh2 + 64);
    gemm_kernel<<<dim3(NP / 128, 4), 256>>>(c3w, p_emb, c3b, p_y3, 192, p_sc2, p_sh2);
    bn_stats_kernel<<<256, 256>>>(p_y3, bn3g, bn3b, p_sc3, p_sh3);
    gemm_kernel<<<dim3(NP / 128, 16), 256>>>(c4w, p_y3, c4b, p_y4, 256, p_sc3, p_sh3);
    bn_stats_kernel<<<1024, 256>>>(p_y4, bn4g, bn4b, p_sc4, p_sh4);
    bn_apply_kernel<<<1024 * NP / 1024, 256>>>((const float4*)p_y4, (float4*)out, p_sc4, p_sh4);

    (void)in_sizes; (void)n_in; (void)out_size;
}

// round 8
// speedup vs baseline: 1.3978x; 1.2106x over previous
#include <cuda_runtime.h>
#include <stdint.h>

#define NP   8192
#define KNN  64
#define EPSF 1e-7f
typedef unsigned long long ull;

// ------------------------- static scratch -------------------------
__device__ float g_px[NP], g_py[NP], g_pz[NP], g_vn[NP];
__device__ __align__(16) float4 g_pt4[NP];
__device__ ull   g_gmax, g_gmin;
__device__ int   g_idx[NP * KNN];
__device__ __align__(16) float g_feat[NP * KNN * 4];
__device__ __align__(16) float g_fd[NP * 4];
__device__ __align__(16) float g_emb[192 * NP];
__device__ __align__(16) float g_y1[64 * NP];
__device__ __align__(16) float g_y3[256 * NP];
__device__ __align__(16) float g_y4[1024 * NP];
__device__ float g_sc1[64],  g_sh1[64];
__device__ float g_sc2[192], g_sh2[192];
__device__ float g_sc3[256], g_sh3[256];
__device__ float g_sc4[1024], g_sh4[1024];

// ------------------------- f32x2 helpers -------------------------
__device__ __forceinline__ ull ffma2(ull a, ull b, ull c) {
    ull d;
    asm("fma.rn.f32x2 %0, %1, %2, %3;" : "=l"(d) : "l"(a), "l"(b), "l"(c));
    return d;
}
__device__ __forceinline__ ull pack2(float x, float y) {
    ull d;
    asm("mov.b64 %0, {%1, %2};" : "=l"(d) : "f"(x), "f"(y));
    return d;
}
__device__ __forceinline__ void unpack2(ull v, float& x, float& y) {
    asm("mov.b64 {%0, %1}, %2;" : "=f"(x), "=f"(y) : "l"(v));
}

// ------------------------- prep -------------------------
__global__ void prep_kernel(const float* __restrict__ pts) {
    int i = blockIdx.x * blockDim.x + threadIdx.x;
    if (i == 0) { g_gmax = 0ULL; g_gmin = ~0ULL; }
    if (i < 64) { g_sc2[i] = 1.0f; g_sh2[i] = 0.0f; }   // identity BN for emb_up rows
    if (i < NP) {
        float x = pts[3 * i], y = pts[3 * i + 1], z = pts[3 * i + 2];
        g_px[i] = x; g_py[i] = y; g_pz[i] = z;
        float rr = x * x + y * y + z * z;
        g_vn[i] = sqrtf(rr);
        g_pt4[i] = make_float4(x, y, z, rr);
    }
}

// ------------------------- KNN: threshold bound + exact rank select -------------------------
#define CAND_CAP 2048
__global__ void __launch_bounds__(256) knn_kernel() {
    const int i = blockIdx.x, tid = threadIdx.x;
    const int lane = tid & 31, warp = tid >> 5;
    __shared__ ull  cand[CAND_CAP];
    __shared__ int  wtmp[8];
    __shared__ unsigned swT[8];
    __shared__ int  wsum[16];

    float4 q4 = g_pt4[i];
    unsigned key[32];
#pragma unroll
    for (int s = 0; s < 32; s++) {
        float4 p = g_pt4[s * 256 + tid];
        float d = q4.w - 2.0f * (q4.x * p.x + q4.y * p.y + q4.z * p.z) + p.w;
        unsigned u = __float_as_uint(d);
        key[s] = u ^ ((u & 0x80000000u) ? 0xFFFFFFFFu : 0x80000000u);
    }

    // --- threshold T: per-warp 8th-smallest lane-min, maxed over warps ---
    unsigned lmin = 0xFFFFFFFFu;
#pragma unroll
    for (int s = 0; s < 32; s++) lmin = (key[s] < lmin) ? key[s] : lmin;
    unsigned val = lmin, Tw = 0;
#pragma unroll
    for (int r = 0; r < 8; r++) {
        unsigned m = __reduce_min_sync(0xFFFFFFFFu, val);
        Tw = m;
        unsigned ball = __ballot_sync(0xFFFFFFFFu, val == m);
        int leader = __ffs(ball) - 1;
        if (lane == leader) val = 0xFFFFFFFFu;
    }
    if (lane == 0) swT[warp] = Tw;
    __syncthreads();
    unsigned T = 0;
#pragma unroll
    for (int w = 0; w < 8; w++) T = (swT[w] > T) ? swT[w] : T;

    // --- count candidates (key <= T) per warp ---
    int c = 0;
#pragma unroll
    for (int s = 0; s < 32; s++) c += (key[s] <= T) ? 1 : 0;
    c = __reduce_add_sync(0xFFFFFFFFu, c);
    if (lane == 0) wtmp[warp] = c;
    __syncthreads();
    int na = 0, off = 0;
#pragma unroll
    for (int w = 0; w < 8; w++) { if (w < warp) off += wtmp[w]; na += wtmp[w]; }

    // --- rare fallback: exact rank-63 key via 32-round binary search ---
    if (na > CAND_CAP) {
        unsigned v = 0u;
        for (int b = 31; b >= 0; b--) {
            unsigned cd = v | (1u << b);
            int cnt = 0;
#pragma unroll
            for (int s = 0; s < 32; s++) cnt += (key[s] < cd) ? 1 : 0;
            cnt = __reduce_add_sync(0xFFFFFFFFu, cnt);
            int bank = (b & 1) << 3;
            if (lane == 0) wsum[bank + warp] = cnt;
            __syncthreads();
            int tot = 0;
#pragma unroll
            for (int w = 0; w < 8; w++) tot += wsum[bank + w];
            if (tot < KNN) v = cd;
        }
        T = v;   // exact rank-63 key value; count(<=T) >= 64 and duplicates assumed < CAP
        int c2 = 0;
#pragma unroll
        for (int s = 0; s < 32; s++) c2 += (key[s] <= T) ? 1 : 0;
        c2 = __reduce_add_sync(0xFFFFFFFFu, c2);
        __syncthreads();
        if (lane == 0) wtmp[warp] = c2;
        __syncthreads();
        na = 0; off = 0;
#pragma unroll
        for (int w = 0; w < 8; w++) { if (w < warp) off += wtmp[w]; na += wtmp[w]; }
        if (na > CAND_CAP) na = CAND_CAP;
    }

    // --- compaction: packed (key, idx) u64 ---
    unsigned lt = (1u << lane) - 1u;
    int o = off;
#pragma unroll
    for (int s = 0; s < 32; s++) {
        bool p = (key[s] <= T);
        unsigned mk = __ballot_sync(0xFFFFFFFFu, p);
        if (p) {
            int slot = o + __popc(mk & lt);
            if (slot < CAND_CAP)
                cand[slot] = (((ull)key[s]) << 32) | (unsigned)(s * 256 + tid);
        }
        o += __popc(mk);
    }
    __syncthreads();

    // --- exact rank of each candidate; ranks 0..63 are the KNN in top_k order ---
    for (int c0 = tid; c0 < na; c0 += 256) {
        ull ct = cand[c0];
        int rank = 0;
        for (int j = 0; j < na; j++) rank += (cand[j] < ct) ? 1 : 0;
        if (rank < KNN) g_idx[i * KNN + rank] = (int)(ct & 0xFFFFFFFFu);
    }
}

// ------------------ per-query rotation-invariant KNN features ------------------
__global__ void __launch_bounds__(64) featknn_kernel() {
    int i = blockIdx.x, k = threadIdx.x;
    __shared__ float sx[64], sy[64], sz[64];
    __shared__ ull sred[64];
    __shared__ float rx[64], ry[64], rz[64];

    int j  = g_idx[i * KNN + k];
    int c0 = g_idx[i * KNN];
    float pcx = g_px[j] - g_px[c0];
    float pcy = g_py[j] - g_py[c0];
    float pcz = g_pz[j] - g_pz[c0];
    float vn  = sqrtf(pcx * pcx + pcy * pcy + pcz * pcz);
    sx[k] = pcx; sy[k] = pcy; sz[k] = pcz;
    rx[k] = pcx; ry[k] = pcy; rz[k] = pcz;
    sred[k] = (((ull)__float_as_uint(vn)) << 32) | (unsigned)(63 - k);
    __syncthreads();
    for (int off = 32; off > 0; off >>= 1) {
        if (k < off) {
            rx[k] += rx[k + off]; ry[k] += ry[k + off]; rz[k] += rz[k + off];
            ull o = sred[k + off];
            if (o > sred[k]) sred[k] = o;
        }
        __syncthreads();
    }
    int id1 = 63 - (int)(sred[0] & 0xFFFFFFFFu);
    float a1x = sx[id1], a1y = sy[id1], a1z = sz[id1];
    float n1 = sqrtf(a1x * a1x + a1y * a1y + a1z * a1z) + EPSF;
    a1x /= n1; a1y /= n1; a1z /= n1;
    float a2x = rx[0] * (1.0f / 64.0f), a2y = ry[0] * (1.0f / 64.0f), a2z = rz[0] * (1.0f / 64.0f);
    float n2 = sqrtf(a2x * a2x + a2y * a2y + a2z * a2z) + EPSF;
    a2x /= n2; a2y /= n2; a2z /= n2;
    float a3x = a1x + 1.5f * a2x, a3y = a1y + 1.5f * a2y, a3z = a1z + 1.5f * a2z;
    float n3 = sqrtf(a3x * a3x + a3y * a3y + a3z * a3z) + EPSF;
    a3x /= n3; a3y /= n3; a3z /= n3;

    float den = vn + EPSF;
    float f1 = (pcx * a1x + pcy * a1y + pcz * a1z) / den;
    float f2 = (pcx * a2x + pcy * a2y + pcz * a2z) / den;
    float f3 = (pcx * a3x + pcy * a3y + pcz * a3z) / den;
    *(float4*)(g_feat + (size_t)(i * KNN + k) * 4) = make_float4(f1, f2, f3, vn);
}

// ------------------ global axes reduce + fd ------------------
__global__ void __launch_bounds__(256) axes_reduce_kernel() {
    int t = blockIdx.x * blockDim.x + threadIdx.x;
    int lane = threadIdx.x & 31;
    unsigned b = __float_as_uint(g_vn[t]);
    ull pmx = (((ull)b) << 32) | (unsigned)(0xFFFFFFFFu - t);
    ull pmn = (((ull)b) << 32) | (unsigned)t;
#pragma unroll
    for (int off = 16; off > 0; off >>= 1) {
        ull ox = __shfl_down_sync(0xFFFFFFFFu, pmx, off);
        ull on = __shfl_down_sync(0xFFFFFFFFu, pmn, off);
        if (ox > pmx) pmx = ox;
        if (on < pmn) pmn = on;
    }
    if (lane == 0) { atomicMax(&g_gmax, pmx); atomicMin(&g_gmin, pmn); }
}

__global__ void fd_kernel() {
    int i = blockIdx.x * blockDim.x + threadIdx.x;
    if (i >= NP) return;
    int i1 = (int)(0xFFFFFFFFu - (unsigned)(g_gmax & 0xFFFFFFFFu));
    int i2 = (int)(g_gmin & 0xFFFFFFFFu);
    float n1 = g_vn[i1] + EPSF;
    float a1x = g_px[i1] / n1, a1y = g_py[i1] / n1, a1z = g_pz[i1] / n1;
    float n2 = g_vn[i2] + EPSF;
    float a2x = g_px[i2] / n2, a2y = g_py[i2] / n2, a2z = g_pz[i2] / n2;
    float a3x = a1x + 1.5f * a2x, a3y = a1y + 1.5f * a2y, a3z = a1z + 1.5f * a2z;
    float n3 = sqrtf(a3x * a3x + a3y * a3y + a3z * a3z) + EPSF;
    a3x /= n3; a3y /= n3; a3z /= n3;
    float x = g_px[i], y = g_py[i], z = g_pz[i], vn = g_vn[i];
    float den = vn + EPSF;
    float f1 = (x * a1x + y * a1y + z * a1z) / den;
    float f2 = (x * a2x + y * a2y + z * a2z) / den;
    float f3 = (x * a3x + y * a3y + z * a3z) / den;
    *(float4*)(g_fd + (size_t)i * 4) = make_float4(f1, f2, f3, vn);
}

// ------------------ fused 5-layer MLP, register-tiled outer product ------------------
#define AST 68
#define WBUF (64 * AST)
#define MLP_SMEM ((WBUF * 5) * 4)
__global__ void __launch_bounds__(256) mlp_kernel(const float* __restrict__ gw0,
                                                  const float* __restrict__ gw1,
                                                  const float* __restrict__ gw2,
                                                  const float* __restrict__ gw3,
                                                  const float* __restrict__ gw4) {
    extern __shared__ float smem[];
    float* W = smem;
    int tid = threadIdx.x;
    int half = tid >> 7, t128 = tid & 127;
    float* A = smem + WBUF + half * 2 * WBUF;
    float* B = A + WBUF;
    int i = blockIdx.x * 2 + half;

    if (t128 < 64) {
        int r = t128;
        float4 f = *(const float4*)(g_feat + (size_t)(i * 64 + r) * 4);
        A[0 * AST + r] = f.x; A[1 * AST + r] = f.y;
        A[2 * AST + r] = f.z; A[3 * AST + r] = f.w;
    }

    int tx = t128 & 7, ty = t128 >> 3;
    float* cur = A; float* nxt = B;
#pragma unroll
    for (int layer = 0; layer < 5; layer++) {
        const int Kc = (layer == 0) ? 4 : 64;
        const float* gw = (layer == 0) ? gw0 : (layer == 1) ? gw1 :
                          (layer == 2) ? gw2 : (layer == 3) ? gw3 : gw4;
        __syncthreads();
        for (int t = tid; t < Kc * 64; t += 256) W[(t >> 6) * AST + (t & 63)] = gw[t];
        __syncthreads();

        ull acc[4][4];
#pragma unroll
        for (int u = 0; u < 4; u++)
#pragma unroll
            for (int q = 0; q < 4; q++) acc[u][q] = 0ULL;

        for (int k = 0; k < Kc; k++) {
            float4 a = *(const float4*)&cur[k * AST + ty * 4];
            const ulonglong2* bp = (const ulonglong2*)&W[k * AST + tx * 8];
            ulonglong2 b01 = bp[0], b23 = bp[1];
            ull d0 = pack2(a.x, a.x), d1 = pack2(a.y, a.y);
            ull d2 = pack2(a.z, a.z), d3 = pack2(a.w, a.w);
            acc[0][0] = ffma2(d0, b01.x, acc[0][0]); acc[0][1] = ffma2(d0, b01.y, acc[0][1]);
            acc[0][2] = ffma2(d0, b23.x, acc[0][2]); acc[0][3] = ffma2(d0, b23.y, acc[0][3]);
            acc[1][0] = ffma2(d1, b01.x, acc[1][0]); acc[1][1] = ffma2(d1, b01.y, acc[1][1]);
            acc[1][2] = ffma2(d1, b23.x, acc[1][2]); acc[1][3] = ffma2(d1, b23.y, acc[1][3]);
            acc[2][0] = ffma2(d2, b01.x, acc[2][0]); acc[2][1] = ffma2(d2, b01.y, acc[2][1]);
            acc[2][2] = ffma2(d2, b23.x, acc[2][2]); acc[2][3] = ffma2(d2, b23.y, acc[2][3]);
            acc[3][0] = ffma2(d3, b01.x, acc[3][0]); acc[3][1] = ffma2(d3, b01.y, acc[3][1]);
            acc[3][2] = ffma2(d3, b23.x, acc[3][2]); acc[3][3] = ffma2(d3, b23.y, acc[3][3]);
        }
#pragma unroll
        for (int jq = 0; jq < 4; jq++) {
            float x0, y0, x1, y1, x2, y2, x3, y3;
            unpack2(acc[0][jq], x0, y0); unpack2(acc[1][jq], x1, y1);
            unpack2(acc[2][jq], x2, y2); unpack2(acc[3][jq], x3, y3);
            int cix = tx * 8 + jq * 2;
            *(float4*)&nxt[cix * AST + ty * 4] =
                make_float4(fmaxf(x0, 0.f), fmaxf(x1, 0.f), fmaxf(x2, 0.f), fmaxf(x3, 0.f));
            *(float4*)&nxt[(cix + 1) * AST + ty * 4] =
                make_float4(fmaxf(y0, 0.f), fmaxf(y1, 0.f), fmaxf(y2, 0.f), fmaxf(y3, 0.f));
        }
        float* t = cur; cur = nxt; nxt = t;
    }
    __syncthreads();
    if (t128 < 64) {
        float m = 0.f;
        const float4* col = (const float4*)&cur[t128 * AST];
#pragma unroll
        for (int q = 0; q < 16; q++) {
            float4 v = col[q];
            m = fmaxf(m, fmaxf(fmaxf(v.x, v.y), fmaxf(v.z, v.w)));
        }
        g_emb[i * 64 + t128] = m;
    }
}

// ------------------ GEMM with fused input-BN+ReLU (sc/sh staged in smem) --------
__global__ void __launch_bounds__(256) gemm_kernel(const float* __restrict__ W,
                                                   const float* __restrict__ X,
                                                   const float* __restrict__ bias,
                                                   float* __restrict__ Y,
                                                   int Kc,
                                                   const float* __restrict__ xsc,
                                                   const float* __restrict__ xsh) {
    __shared__ float sW[16][68];
    __shared__ float sX[16][132];
    __shared__ float ssc[256], ssh[256];
    int tid = threadIdx.x;
    int bm = blockIdx.y * 64, bn = blockIdx.x * 128;
    int tx = tid & 15, ty = tid >> 4;
    if (xsc) {
        for (int t = tid; t < Kc; t += 256) { ssc[t] = xsc[t]; ssh[t] = xsh[t]; }
    }
    ull acc[4][4];
#pragma unroll
    for (int u = 0; u < 4; u++)
#pragma unroll
        for (int q = 0; q < 4; q++) acc[u][q] = 0ULL;
    __syncthreads();

    for (int k0 = 0; k0 < Kc; k0 += 16) {
        for (int t = tid; t < 1024; t += 256) {
            int kk = t & 15, m = t >> 4;
            float val = 0.f;
            if (k0 + kk < Kc) val = W[(size_t)(bm + m) * Kc + k0 + kk];
            sW[kk][m] = val;
        }
        for (int t = tid; t < 2048; t += 256) {
            int n = t & 127, kk = t >> 7;
            float val = 0.f;
            if (k0 + kk < Kc) {
                val = X[(size_t)(k0 + kk) * NP + bn + n];
                if (xsc) val = fmaxf(val * ssc[k0 + kk] + ssh[k0 + kk], 0.f);
            }
            sX[kk][n] = val;
        }
        __syncthreads();
#pragma unroll
        for (int kk = 0; kk < 16; kk++) {
            float4 a = *(const float4*)&sW[kk][ty * 4];
            const ulonglong2* bx = (const ulonglong2*)&sX[kk][tx * 8];
            ulonglong2 b01 = bx[0];
            ulonglong2 b23 = bx[1];
            float av[4] = {a.x, a.y, a.z, a.w};
#pragma unroll
            for (int u = 0; u < 4; u++) {
                ull aa = pack2(av[u], av[u]);
                acc[u][0] = ffma2(aa, b01.x, acc[u][0]);
                acc[u][1] = ffma2(aa, b01.y, acc[u][1]);
                acc[u][2] = ffma2(aa, b23.x, acc[u][2]);
                acc[u][3] = ffma2(aa, b23.y, acc[u][3]);
            }
        }
        __syncthreads();
    }
    int m0 = bm + ty * 4;
#pragma unroll
    for (int u = 0; u < 4; u++) {
        float bv = bias[m0 + u];
        float o[8];
#pragma unroll
        for (int q = 0; q < 4; q++) {
            float vx, vy; unpack2(acc[u][q], vx, vy);
            o[q * 2] = vx + bv; o[q * 2 + 1] = vy + bv;
        }
        float* yrow = Y + (size_t)(m0 + u) * NP + bn + tx * 8;
        *(float4*)yrow       = make_float4(o[0], o[1], o[2], o[3]);
        *(float4*)(yrow + 4) = make_float4(o[4], o[5], o[6], o[7]);
    }
}

// ------------------ BatchNorm stats (one pass) ------------------
__global__ void __launch_bounds__(256) bn_stats_kernel(const float* __restrict__ Y,
                                                       const float* __restrict__ gamma,
                                                       const float* __restrict__ beta,
                                                       float* __restrict__ sc,
                                                       float* __restrict__ sh) {
    int ch = blockIdx.x, tid = threadIdx.x;
    const float4* row = (const float4*)(Y + (size_t)ch * NP);
    float s = 0.f, s2 = 0.f;
    for (int t = tid; t < NP / 4; t += 256) {
        float4 v = row[t];
        s  += v.x + v.y + v.z + v.w;
        s2 += v.x * v.x + v.y * v.y + v.z * v.z + v.w * v.w;
    }
    __shared__ float r1[256], r2[256];
    r1[tid] = s; r2[tid] = s2; __syncthreads();
    for (int off = 128; off > 0; off >>= 1) {
        if (tid < off) { r1[tid] += r1[tid + off]; r2[tid] += r2[tid + off]; }
        __syncthreads();
    }
    if (tid == 0) {
        float mu = r1[0] * (1.0f / NP);
        float var = r2[0] * (1.0f / NP) - mu * mu;
        var = fmaxf(var, 0.f);
        float s0 = gamma[ch] * rsqrtf(var + 1e-5f);
        sc[ch] = s0;
        sh[ch] = beta[ch] - mu * s0;
    }
}

__global__ void bn_apply_kernel(const float4* __restrict__ Yin, float4* __restrict__ Yout,
                                const float* __restrict__ sc, const float* __restrict__ sh) {
    int idx = blockIdx.x * blockDim.x + threadIdx.x;
    int ch = idx >> 11;
    float s0 = sc[ch], s1 = sh[ch];
    float4 v = Yin[idx];
    v.x = fmaxf(v.x * s0 + s1, 0.f);
    v.y = fmaxf(v.y * s0 + s1, 0.f);
    v.z = fmaxf(v.z * s0 + s1, 0.f);
    v.w = fmaxf(v.w * s0 + s1, 0.f);
    Yout[idx] = v;
}

// ------------------------- launch -------------------------
extern "C" void kernel_launch(void* const* d_in, const int* in_sizes, int n_in,
                              void* d_out, int out_size) {
    const float* pts  = (const float*)d_in[0];
    const float* gw0  = (const float*)d_in[1];
    const float* gw1  = (const float*)d_in[2];
    const float* gw2  = (const float*)d_in[3];
    const float* gw3  = (const float*)d_in[4];
    const float* gw4  = (const float*)d_in[5];
    const float* c1w  = (const float*)d_in[6];
    const float* c1b  = (const float*)d_in[7];
    const float* bn1g = (const float*)d_in[8];
    const float* bn1b = (const float*)d_in[9];
    const float* c2w  = (const float*)d_in[10];
    const float* c2b  = (const float*)d_in[11];
    const float* bn2g = (const float*)d_in[12];
    const float* bn2b = (const float*)d_in[13];
    const float* c3w  = (const float*)d_in[14];
    const float* c3b  = (const float*)d_in[15];
    const float* bn3g = (const float*)d_in[16];
    const float* bn3b = (const float*)d_in[17];
    const float* c4w  = (const float*)d_in[18];
    const float* c4b  = (const float*)d_in[19];
    const float* bn4g = (const float*)d_in[20];
    const float* bn4b = (const float*)d_in[21];
    float* out = (float*)d_out;

    float *p_fd, *p_emb, *p_y1, *p_y3, *p_y4;
    float *p_sc1, *p_sh1, *p_sc2, *p_sh2, *p_sc3, *p_sh3, *p_sc4, *p_sh4;
    cudaGetSymbolAddress((void**)&p_fd,  g_fd);
    cudaGetSymbolAddress((void**)&p_emb, g_emb);
    cudaGetSymbolAddress((void**)&p_y1,  g_y1);
    cudaGetSymbolAddress((void**)&p_y3,  g_y3);
    cudaGetSymbolAddress((void**)&p_y4,  g_y4);
    cudaGetSymbolAddress((void**)&p_sc1, g_sc1);
    cudaGetSymbolAddress((void**)&p_sh1, g_sh1);
    cudaGetSymbolAddress((void**)&p_sc2, g_sc2);
    cudaGetSymbolAddress((void**)&p_sh2, g_sh2);
    cudaGetSymbolAddress((void**)&p_sc3, g_sc3);
    cudaGetSymbolAddress((void**)&p_sh3, g_sh3);
    cudaGetSymbolAddress((void**)&p_sc4, g_sc4);
    cudaGetSymbolAddress((void**)&p_sh4, g_sh4);

    cudaFuncSetAttribute(mlp_kernel, cudaFuncAttributeMaxDynamicSharedMemorySize, MLP_SMEM);

    prep_kernel<<<(NP + 255) / 256, 256>>>(pts);                    // 1
    knn_kernel<<<NP, 256>>>();                                      // 2
    featknn_kernel<<<NP, 64>>>();                                   // 3
    mlp_kernel<<<NP / 2, 256, MLP_SMEM>>>(gw0, gw1, gw2, gw3, gw4); // 4 (ncu captures #4)
    axes_reduce_kernel<<<NP / 256, 256>>>();                        // 5
    fd_kernel<<<(NP + 255) / 256, 256>>>();                         // 6

    gemm_kernel<<<dim3(NP / 128, 1), 256>>>(c1w, p_fd, c1b, p_y1, 4, nullptr, nullptr);
    bn_stats_kernel<<<64, 256>>>(p_y1, bn1g, bn1b, p_sc1, p_sh1);
    gemm_kernel<<<dim3(NP / 128, 2), 256>>>(c2w, p_y1, c2b, p_emb + 64 * NP, 64, p_sc1, p_sh1);
    bn_stats_kernel<<<128, 256>>>(p_emb + 64 * NP, bn2g, bn2b, p_sc2 + 64, p_sh2 + 64);
    gemm_kernel<<<dim3(NP / 128, 4), 256>>>(c3w, p_emb, c3b, p_y3, 192, p_sc2, p_sh2);
    bn_stats_kernel<<<256, 256>>>(p_y3, bn3g, bn3b, p_sc3, p_sh3);
    gemm_kernel<<<dim3(NP / 128, 16), 256>>>(c4w, p_y3, c4b, p_y4, 256, p_sc3, p_sh3);
    bn_stats_kernel<<<1024, 256>>>(p_y4, bn4g, bn4b, p_sc4, p_sh4);
    bn_apply_kernel<<<1024 * NP / 1024, 256>>>((const float4*)p_y4, (float4*)out, p_sc4, p_sh4);

    (void)in_sizes; (void)n_in; (void)out_size;
}

// round 9
// speedup vs baseline: 1.7840x; 1.2763x over previous
#include <cuda_runtime.h>
#include <stdint.h>

#define NP   8192
#define KNN  64
#define EPSF 1e-7f
typedef unsigned long long ull;

// ------------------------- static scratch -------------------------
__device__ float g_px[NP], g_py[NP], g_pz[NP], g_vn[NP];
__device__ __align__(16) float4 g_pt4[NP];
__device__ ull   g_gmax, g_gmin;
__device__ int   g_idx[NP * KNN];
__device__ __align__(16) float g_feat[NP * KNN * 4];
__device__ __align__(16) float g_fd[NP * 4];
__device__ __align__(16) float g_emb[192 * NP];
__device__ __align__(16) float g_y1[64 * NP];
__device__ __align__(16) float g_y3[256 * NP];
__device__ __align__(16) float g_y4[1024 * NP];
__device__ float g_sc1[64],  g_sh1[64];
__device__ float g_sc2[192], g_sh2[192];
__device__ float g_sc3[256], g_sh3[256];
__device__ float g_sc4[1024], g_sh4[1024];

// ------------------------- f32x2 helpers -------------------------
__device__ __forceinline__ ull ffma2(ull a, ull b, ull c) {
    ull d;
    asm("fma.rn.f32x2 %0, %1, %2, %3;" : "=l"(d) : "l"(a), "l"(b), "l"(c));
    return d;
}
__device__ __forceinline__ ull pack2(float x, float y) {
    ull d;
    asm("mov.b64 %0, {%1, %2};" : "=l"(d) : "f"(x), "f"(y));
    return d;
}
__device__ __forceinline__ void unpack2(ull v, float& x, float& y) {
    asm("mov.b64 {%0, %1}, %2;" : "=f"(x), "=f"(y) : "l"(v));
}

// ------------------------- prep -------------------------
__global__ void prep_kernel(const float* __restrict__ pts) {
    int i = blockIdx.x * blockDim.x + threadIdx.x;
    if (i == 0) { g_gmax = 0ULL; g_gmin = ~0ULL; }
    if (i < 64) { g_sc2[i] = 1.0f; g_sh2[i] = 0.0f; }   // identity BN for emb_up rows
    if (i < NP) {
        float x = pts[3 * i], y = pts[3 * i + 1], z = pts[3 * i + 2];
        g_px[i] = x; g_py[i] = y; g_pz[i] = z;
        float rr = x * x + y * y + z * z;
        g_vn[i] = sqrtf(rr);
        g_pt4[i] = make_float4(x, y, z, rr);
    }
}

// ------------------------- KNN: threshold bound + exact rank select -------------------------
#define CAND_CAP 2048
__global__ void __launch_bounds__(256) knn_kernel() {
    const int i = blockIdx.x, tid = threadIdx.x;
    const int lane = tid & 31, warp = tid >> 5;
    __shared__ ull  cand[CAND_CAP];
    __shared__ int  wtmp[8];
    __shared__ unsigned swT[8];
    __shared__ int  wsum[16];

    float4 q4 = g_pt4[i];
    unsigned key[32];
#pragma unroll
    for (int s = 0; s < 32; s++) {
        float4 p = g_pt4[s * 256 + tid];
        float d = q4.w - 2.0f * (q4.x * p.x + q4.y * p.y + q4.z * p.z) + p.w;
        unsigned u = __float_as_uint(d);
        key[s] = u ^ ((u & 0x80000000u) ? 0xFFFFFFFFu : 0x80000000u);
    }

    // --- threshold T: per-warp 8th-smallest lane-min, maxed over warps ---
    unsigned lmin = 0xFFFFFFFFu;
#pragma unroll
    for (int s = 0; s < 32; s++) lmin = (key[s] < lmin) ? key[s] : lmin;
    unsigned val = lmin, Tw = 0;
#pragma unroll
    for (int r = 0; r < 8; r++) {
        unsigned m = __reduce_min_sync(0xFFFFFFFFu, val);
        Tw = m;
        unsigned ball = __ballot_sync(0xFFFFFFFFu, val == m);
        int leader = __ffs(ball) - 1;
        if (lane == leader) val = 0xFFFFFFFFu;
    }
    if (lane == 0) swT[warp] = Tw;
    __syncthreads();
    unsigned T = 0;
#pragma unroll
    for (int w = 0; w < 8; w++) T = (swT[w] > T) ? swT[w] : T;

    // --- count candidates (key <= T) per warp ---
    int c = 0;
#pragma unroll
    for (int s = 0; s < 32; s++) c += (key[s] <= T) ? 1 : 0;
    c = __reduce_add_sync(0xFFFFFFFFu, c);
    if (lane == 0) wtmp[warp] = c;
    __syncthreads();
    int na = 0, off = 0;
#pragma unroll
    for (int w = 0; w < 8; w++) { if (w < warp) off += wtmp[w]; na += wtmp[w]; }

    // --- rare fallback: exact rank-63 key via 32-round binary search ---
    if (na > CAND_CAP) {
        unsigned v = 0u;
        for (int b = 31; b >= 0; b--) {
            unsigned cd = v | (1u << b);
            int cnt = 0;
#pragma unroll
            for (int s = 0; s < 32; s++) cnt += (key[s] < cd) ? 1 : 0;
            cnt = __reduce_add_sync(0xFFFFFFFFu, cnt);
            int bank = (b & 1) << 3;
            if (lane == 0) wsum[bank + warp] = cnt;
            __syncthreads();
            int tot = 0;
#pragma unroll
            for (int w = 0; w < 8; w++) tot += wsum[bank + w];
            if (tot < KNN) v = cd;
        }
        T = v;
        int c2 = 0;
#pragma unroll
        for (int s = 0; s < 32; s++) c2 += (key[s] <= T) ? 1 : 0;
        c2 = __reduce_add_sync(0xFFFFFFFFu, c2);
        __syncthreads();
        if (lane == 0) wtmp[warp] = c2;
        __syncthreads();
        na = 0; off = 0;
#pragma unroll
        for (int w = 0; w < 8; w++) { if (w < warp) off += wtmp[w]; na += wtmp[w]; }
        if (na > CAND_CAP) na = CAND_CAP;
    }

    // --- compaction: packed (key, idx) u64 ---
    unsigned lt = (1u << lane) - 1u;
    int o = off;
#pragma unroll
    for (int s = 0; s < 32; s++) {
        bool p = (key[s] <= T);
        unsigned mk = __ballot_sync(0xFFFFFFFFu, p);
        if (p) {
            int slot = o + __popc(mk & lt);
            if (slot < CAND_CAP)
                cand[slot] = (((ull)key[s]) << 32) | (unsigned)(s * 256 + tid);
        }
        o += __popc(mk);
    }
    __syncthreads();

    // --- exact rank of each candidate; ranks 0..63 are the KNN in top_k order ---
    for (int c0 = tid; c0 < na; c0 += 256) {
        ull ct = cand[c0];
        int rank = 0;
        for (int j = 0; j < na; j++) rank += (cand[j] < ct) ? 1 : 0;
        if (rank < KNN) g_idx[i * KNN + rank] = (int)(ct & 0xFFFFFFFFu);
    }
}

// ------------------ per-query rotation-invariant KNN features ------------------
__global__ void __launch_bounds__(64) featknn_kernel() {
    int i = blockIdx.x, k = threadIdx.x;
    __shared__ float sx[64], sy[64], sz[64];
    __shared__ ull sred[64];
    __shared__ float rx[64], ry[64], rz[64];

    int j  = g_idx[i * KNN + k];
    int c0 = g_idx[i * KNN];
    float pcx = g_px[j] - g_px[c0];
    float pcy = g_py[j] - g_py[c0];
    float pcz = g_pz[j] - g_pz[c0];
    float vn  = sqrtf(pcx * pcx + pcy * pcy + pcz * pcz);
    sx[k] = pcx; sy[k] = pcy; sz[k] = pcz;
    rx[k] = pcx; ry[k] = pcy; rz[k] = pcz;
    sred[k] = (((ull)__float_as_uint(vn)) << 32) | (unsigned)(63 - k);
    __syncthreads();
    for (int off = 32; off > 0; off >>= 1) {
        if (k < off) {
            rx[k] += rx[k + off]; ry[k] += ry[k + off]; rz[k] += rz[k + off];
            ull o = sred[k + off];
            if (o > sred[k]) sred[k] = o;
        }
        __syncthreads();
    }
    int id1 = 63 - (int)(sred[0] & 0xFFFFFFFFu);
    float a1x = sx[id1], a1y = sy[id1], a1z = sz[id1];
    float n1 = sqrtf(a1x * a1x + a1y * a1y + a1z * a1z) + EPSF;
    a1x /= n1; a1y /= n1; a1z /= n1;
    float a2x = rx[0] * (1.0f / 64.0f), a2y = ry[0] * (1.0f / 64.0f), a2z = rz[0] * (1.0f / 64.0f);
    float n2 = sqrtf(a2x * a2x + a2y * a2y + a2z * a2z) + EPSF;
    a2x /= n2; a2y /= n2; a2z /= n2;
    float a3x = a1x + 1.5f * a2x, a3y = a1y + 1.5f * a2y, a3z = a1z + 1.5f * a2z;
    float n3 = sqrtf(a3x * a3x + a3y * a3y + a3z * a3z) + EPSF;
    a3x /= n3; a3y /= n3; a3z /= n3;

    float den = vn + EPSF;
    float f1 = (pcx * a1x + pcy * a1y + pcz * a1z) / den;
    float f2 = (pcx * a2x + pcy * a2y + pcz * a2z) / den;
    float f3 = (pcx * a3x + pcy * a3y + pcz * a3z) / den;
    *(float4*)(g_feat + (size_t)(i * KNN + k) * 4) = make_float4(f1, f2, f3, vn);
}

// ------------------ global axes reduce + fd ------------------
__global__ void __launch_bounds__(256) axes_reduce_kernel() {
    int t = blockIdx.x * blockDim.x + threadIdx.x;
    int lane = threadIdx.x & 31;
    unsigned b = __float_as_uint(g_vn[t]);
    ull pmx = (((ull)b) << 32) | (unsigned)(0xFFFFFFFFu - t);
    ull pmn = (((ull)b) << 32) | (unsigned)t;
#pragma unroll
    for (int off = 16; off > 0; off >>= 1) {
        ull ox = __shfl_down_sync(0xFFFFFFFFu, pmx, off);
        ull on = __shfl_down_sync(0xFFFFFFFFu, pmn, off);
        if (ox > pmx) pmx = ox;
        if (on < pmn) pmn = on;
    }
    if (lane == 0) { atomicMax(&g_gmax, pmx); atomicMin(&g_gmin, pmn); }
}

__global__ void fd_kernel() {
    int i = blockIdx.x * blockDim.x + threadIdx.x;
    if (i >= NP) return;
    int i1 = (int)(0xFFFFFFFFu - (unsigned)(g_gmax & 0xFFFFFFFFu));
    int i2 = (int)(g_gmin & 0xFFFFFFFFu);
    float n1 = g_vn[i1] + EPSF;
    float a1x = g_px[i1] / n1, a1y = g_py[i1] / n1, a1z = g_pz[i1] / n1;
    float n2 = g_vn[i2] + EPSF;
    float a2x = g_px[i2] / n2, a2y = g_py[i2] / n2, a2z = g_pz[i2] / n2;
    float a3x = a1x + 1.5f * a2x, a3y = a1y + 1.5f * a2y, a3z = a1z + 1.5f * a2z;
    float n3 = sqrtf(a3x * a3x + a3y * a3y + a3z * a3z) + EPSF;
    a3x /= n3; a3y /= n3; a3z /= n3;
    float x = g_px[i], y = g_py[i], z = g_pz[i], vn = g_vn[i];
    float den = vn + EPSF;
    float f1 = (x * a1x + y * a1y + z * a1z) / den;
    float f2 = (x * a2x + y * a2y + z * a2z) / den;
    float f3 = (x * a3x + y * a3y + z * a3z) / den;
    *(float4*)(g_fd + (size_t)i * 4) = make_float4(f1, f2, f3, vn);
}

// ------------------ fused 5-layer MLP, register-tiled outer product ------------------
// 2 points/block, 128 thr/point, thread tile 4 rows x 8 cols.
// Weights staged per layer in a bank-conflict-free layout (4-float gap after col 32).
#define AST 68
#define WST 72
#define ABUF (64 * AST)                 // 4352 floats per activation buffer
#define WBUF_W (64 * WST)               // 4608 floats for weights
#define MLP_SMEM ((WBUF_W + 4 * ABUF) * 4)   // 88,064 B -> 2 blocks/SM
__global__ void __launch_bounds__(256, 2) mlp_kernel(const float* __restrict__ gw0,
                                                     const float* __restrict__ gw1,
                                                     const float* __restrict__ gw2,
                                                     const float* __restrict__ gw3,
                                                     const float* __restrict__ gw4) {
    extern __shared__ float smem[];
    float* W = smem;                                    // [64][WST], swizzled cols
    int tid = threadIdx.x;
    int half = tid >> 7, t128 = tid & 127;
    float* A = smem + WBUF_W + half * 2 * ABUF;
    float* B = A + ABUF;
    int i = blockIdx.x * 2 + half;

    if (t128 < 64) {
        int r = t128;
        float4 f = *(const float4*)(g_feat + (size_t)(i * 64 + r) * 4);
        A[0 * AST + r] = f.x; A[1 * AST + r] = f.y;
        A[2 * AST + r] = f.z; A[3 * AST + r] = f.w;
    }

    int tx = t128 & 7, ty = t128 >> 3;
    int wcol = tx * 8 + ((tx >> 2) << 2);               // conflict-free column base
    float* cur = A; float* nxt = B;
#pragma unroll
    for (int layer = 0; layer < 5; layer++) {
        const int Kc = (layer == 0) ? 4 : 64;
        const float* gw = (layer == 0) ? gw0 : (layer == 1) ? gw1 :
                          (layer == 2) ? gw2 : (layer == 3) ? gw3 : gw4;
        __syncthreads();
        for (int t = tid; t < Kc * 64; t += 256) {
            int col = t & 63;
            W[(t >> 6) * WST + col + ((col >> 5) << 2)] = gw[t];
        }
        __syncthreads();

        ull acc[4][4];
#pragma unroll
        for (int u = 0; u < 4; u++)
#pragma unroll
            for (int q = 0; q < 4; q++) acc[u][q] = 0ULL;

#pragma unroll 4
        for (int k = 0; k < Kc; k++) {
            float4 a = *(const float4*)&cur[k * AST + ty * 4];
            const ulonglong2* bp = (const ulonglong2*)&W[k * WST + wcol];
            ulonglong2 b01 = bp[0], b23 = bp[1];
            ull d0 = pack2(a.x, a.x), d1 = pack2(a.y, a.y);
            ull d2 = pack2(a.z, a.z), d3 = pack2(a.w, a.w);
            acc[0][0] = ffma2(d0, b01.x, acc[0][0]); acc[0][1] = ffma2(d0, b01.y, acc[0][1]);
            acc[0][2] = ffma2(d0, b23.x, acc[0][2]); acc[0][3] = ffma2(d0, b23.y, acc[0][3]);
            acc[1][0] = ffma2(d1, b01.x, acc[1][0]); acc[1][1] = ffma2(d1, b01.y, acc[1][1]);
            acc[1][2] = ffma2(d1, b23.x, acc[1][2]); acc[1][3] = ffma2(d1, b23.y, acc[1][3]);
            acc[2][0] = ffma2(d2, b01.x, acc[2][0]); acc[2][1] = ffma2(d2, b01.y, acc[2][1]);
            acc[2][2] = ffma2(d2, b23.x, acc[2][2]); acc[2][3] = ffma2(d2, b23.y, acc[2][3]);
            acc[3][0] = ffma2(d3, b01.x, acc[3][0]); acc[3][1] = ffma2(d3, b01.y, acc[3][1]);
            acc[3][2] = ffma2(d3, b23.x, acc[3][2]); acc[3][3] = ffma2(d3, b23.y, acc[3][3]);
        }
#pragma unroll
        for (int jq = 0; jq < 4; jq++) {
            float x0, y0, x1, y1, x2, y2, x3, y3;
            unpack2(acc[0][jq], x0, y0); unpack2(acc[1][jq], x1, y1);
            unpack2(acc[2][jq], x2, y2); unpack2(acc[3][jq], x3, y3);
            int cix = tx * 8 + jq * 2;
            *(float4*)&nxt[cix * AST + ty * 4] =
                make_float4(fmaxf(x0, 0.f), fmaxf(x1, 0.f), fmaxf(x2, 0.f), fmaxf(x3, 0.f));
            *(float4*)&nxt[(cix + 1) * AST + ty * 4] =
                make_float4(fmaxf(y0, 0.f), fmaxf(y1, 0.f), fmaxf(y2, 0.f), fmaxf(y3, 0.f));
        }
        float* t = cur; cur = nxt; nxt = t;
    }
    __syncthreads();
    if (t128 < 64) {
        float m = 0.f;
        const float4* col = (const float4*)&cur[t128 * AST];
#pragma unroll
        for (int q = 0; q < 16; q++) {
            float4 v = col[q];
            m = fmaxf(m, fmaxf(fmaxf(v.x, v.y), fmaxf(v.z, v.w)));
        }
        g_emb[i * 64 + t128] = m;
    }
}

// ------------------ GEMM with fused input-BN+ReLU (sc/sh staged in smem) --------
__global__ void __launch_bounds__(256) gemm_kernel(const float* __restrict__ W,
                                                   const float* __restrict__ X,
                                                   const float* __restrict__ bias,
                                                   float* __restrict__ Y,
                                                   int Kc,
                                                   const float* __restrict__ xsc,
                                                   const float* __restrict__ xsh) {
    __shared__ float sW[16][68];
    __shared__ float sX[16][132];
    __shared__ float ssc[256], ssh[256];
    int tid = threadIdx.x;
    int bm = blockIdx.y * 64, bn = blockIdx.x * 128;
    int tx = tid & 15, ty = tid >> 4;
    if (xsc) {
        for (int t = tid; t < Kc; t += 256) { ssc[t] = xsc[t]; ssh[t] = xsh[t]; }
    }
    ull acc[4][4];
#pragma unroll
    for (int u = 0; u < 4; u++)
#pragma unroll
        for (int q = 0; q < 4; q++) acc[u][q] = 0ULL;
    __syncthreads();

    for (int k0 = 0; k0 < Kc; k0 += 16) {
        for (int t = tid; t < 1024; t += 256) {
            int kk = t & 15, m = t >> 4;
            float val = 0.f;
            if (k0 + kk < Kc) val = W[(size_t)(bm + m) * Kc + k0 + kk];
            sW[kk][m] = val;
        }
        for (int t = tid; t < 2048; t += 256) {
            int n = t & 127, kk = t >> 7;
            float val = 0.f;
            if (k0 + kk < Kc) {
                val = X[(size_t)(k0 + kk) * NP + bn + n];
                if (xsc) val = fmaxf(val * ssc[k0 + kk] + ssh[k0 + kk], 0.f);
            }
            sX[kk][n] = val;
        }
        __syncthreads();
#pragma unroll
        for (int kk = 0; kk < 16; kk++) {
            float4 a = *(const float4*)&sW[kk][ty * 4];
            const ulonglong2* bx = (const ulonglong2*)&sX[kk][tx * 8];
            ulonglong2 b01 = bx[0];
            ulonglong2 b23 = bx[1];
            float av[4] = {a.x, a.y, a.z, a.w};
#pragma unroll
            for (int u = 0; u < 4; u++) {
                ull aa = pack2(av[u], av[u]);
                acc[u][0] = ffma2(aa, b01.x, acc[u][0]);
                acc[u][1] = ffma2(aa, b01.y, acc[u][1]);
                acc[u][2] = ffma2(aa, b23.x, acc[u][2]);
                acc[u][3] = ffma2(aa, b23.y, acc[u][3]);
            }
        }
        __syncthreads();
    }
    int m0 = bm + ty * 4;
#pragma unroll
    for (int u = 0; u < 4; u++) {
        float bv = bias[m0 + u];
        float o[8];
#pragma unroll
        for (int q = 0; q < 4; q++) {
            float vx, vy; unpack2(acc[u][q], vx, vy);
            o[q * 2] = vx + bv; o[q * 2 + 1] = vy + bv;
        }
        float* yrow = Y + (size_t)(m0 + u) * NP + bn + tx * 8;
        *(float4*)yrow       = make_float4(o[0], o[1], o[2], o[3]);
        *(float4*)(yrow + 4) = make_float4(o[4], o[5], o[6], o[7]);
    }
}

// ------------------ BatchNorm stats (one pass) ------------------
__global__ void __launch_bounds__(256) bn_stats_kernel(const float* __restrict__ Y,
                                                       const float* __restrict__ gamma,
                                                       const float* __restrict__ beta,
                                                       float* __restrict__ sc,
                                                       float* __restrict__ sh) {
    int ch = blockIdx.x, tid = threadIdx.x;
    const float4* row = (const float4*)(Y + (size_t)ch * NP);
    float s = 0.f, s2 = 0.f;
    for (int t = tid; t < NP / 4; t += 256) {
        float4 v = row[t];
        s  += v.x + v.y + v.z + v.w;
        s2 += v.x * v.x + v.y * v.y + v.z * v.z + v.w * v.w;
    }
    __shared__ float r1[256], r2[256];
    r1[tid] = s; r2[tid] = s2; __syncthreads();
    for (int off = 128; off > 0; off >>= 1) {
        if (tid < off) { r1[tid] += r1[tid + off]; r2[tid] += r2[tid + off]; }
        __syncthreads();
    }
    if (tid == 0) {
        float mu = r1[0] * (1.0f / NP);
        float var = r2[0] * (1.0f / NP) - mu * mu;
        var = fmaxf(var, 0.f);
        float s0 = gamma[ch] * rsqrtf(var + 1e-5f);
        sc[ch] = s0;
        sh[ch] = beta[ch] - mu * s0;
    }
}

__global__ void bn_apply_kernel(const float4* __restrict__ Yin, float4* __restrict__ Yout,
                                const float* __restrict__ sc, const float* __restrict__ sh) {
    int idx = blockIdx.x * blockDim.x + threadIdx.x;
    int ch = idx >> 11;
    float s0 = sc[ch], s1 = sh[ch];
    float4 v = Yin[idx];
    v.x = fmaxf(v.x * s0 + s1, 0.f);
    v.y = fmaxf(v.y * s0 + s1, 0.f);
    v.z = fmaxf(v.z * s0 + s1, 0.f);
    v.w = fmaxf(v.w * s0 + s1, 0.f);
    Yout[idx] = v;
}

// ------------------------- launch -------------------------
extern "C" void kernel_launch(void* const* d_in, const int* in_sizes, int n_in,
                              void* d_out, int out_size) {
    const float* pts  = (const float*)d_in[0];
    const float* gw0  = (const float*)d_in[1];
    const float* gw1  = (const float*)d_in[2];
    const float* gw2  = (const float*)d_in[3];
    const float* gw3  = (const float*)d_in[4];
    const float* gw4  = (const float*)d_in[5];
    const float* c1w  = (const float*)d_in[6];
    const float* c1b  = (const float*)d_in[7];
    const float* bn1g = (const float*)d_in[8];
    const float* bn1b = (const float*)d_in[9];
    const float* c2w  = (const float*)d_in[10];
    const float* c2b  = (const float*)d_in[11];
    const float* bn2g = (const float*)d_in[12];
    const float* bn2b = (const float*)d_in[13];
    const float* c3w  = (const float*)d_in[14];
    const float* c3b  = (const float*)d_in[15];
    const float* bn3g = (const float*)d_in[16];
    const float* bn3b = (const float*)d_in[17];
    const float* c4w  = (const float*)d_in[18];
    const float* c4b  = (const float*)d_in[19];
    const float* bn4g = (const float*)d_in[20];
    const float* bn4b = (const float*)d_in[21];
    float* out = (float*)d_out;

    float *p_fd, *p_emb, *p_y1, *p_y3, *p_y4;
    float *p_sc1, *p_sh1, *p_sc2, *p_sh2, *p_sc3, *p_sh3, *p_sc4, *p_sh4;
    cudaGetSymbolAddress((void**)&p_fd,  g_fd);
    cudaGetSymbolAddress((void**)&p_emb, g_emb);
    cudaGetSymbolAddress((void**)&p_y1,  g_y1);
    cudaGetSymbolAddress((void**)&p_y3,  g_y3);
    cudaGetSymbolAddress((void**)&p_y4,  g_y4);
    cudaGetSymbolAddress((void**)&p_sc1, g_sc1);
    cudaGetSymbolAddress((void**)&p_sh1, g_sh1);
    cudaGetSymbolAddress((void**)&p_sc2, g_sc2);
    cudaGetSymbolAddress((void**)&p_sh2, g_sh2);
    cudaGetSymbolAddress((void**)&p_sc3, g_sc3);
    cudaGetSymbolAddress((void**)&p_sh3, g_sh3);
    cudaGetSymbolAddress((void**)&p_sc4, g_sc4);
    cudaGetSymbolAddress((void**)&p_sh4, g_sh4);

    cudaFuncSetAttribute(mlp_kernel, cudaFuncAttributeMaxDynamicSharedMemorySize, MLP_SMEM);

    prep_kernel<<<(NP + 255) / 256, 256>>>(pts);                    // 1
    knn_kernel<<<NP, 256>>>();                                      // 2
    featknn_kernel<<<NP, 64>>>();                                   // 3
    mlp_kernel<<<NP / 2, 256, MLP_SMEM>>>(gw0, gw1, gw2, gw3, gw4); // 4 (ncu captures #4)
    axes_reduce_kernel<<<NP / 256, 256>>>();                        // 5
    fd_kernel<<<(NP + 255) / 256, 256>>>();                         // 6

    gemm_kernel<<<dim3(NP / 128, 1), 256>>>(c1w, p_fd, c1b, p_y1, 4, nullptr, nullptr);
    bn_stats_kernel<<<64, 256>>>(p_y1, bn1g, bn1b, p_sc1, p_sh1);
    gemm_kernel<<<dim3(NP / 128, 2), 256>>>(c2w, p_y1, c2b, p_emb + 64 * NP, 64, p_sc1, p_sh1);
    bn_stats_kernel<<<128, 256>>>(p_emb + 64 * NP, bn2g, bn2b, p_sc2 + 64, p_sh2 + 64);
    gemm_kernel<<<dim3(NP / 128, 4), 256>>>(c3w, p_emb, c3b, p_y3, 192, p_sc2, p_sh2);
    bn_stats_kernel<<<256, 256>>>(p_y3, bn3g, bn3b, p_sc3, p_sh3);
    gemm_kernel<<<dim3(NP / 128, 16), 256>>>(c4w, p_y3, c4b, p_y4, 256, p_sc3, p_sh3);
    bn_stats_kernel<<<1024, 256>>>(p_y4, bn4g, bn4b, p_sc4, p_sh4);
    bn_apply_kernel<<<1024 * NP / 1024, 256>>>((const float4*)p_y4, (float4*)out, p_sc4, p_sh4);

    (void)in_sizes; (void)n_in; (void)out_size;
}

// round 12
// speedup vs baseline: 2.0609x; 1.1552x over previous
#include <cuda_runtime.h>
#include <cuda_bf16.h>
#include <stdint.h>

#define NP   8192
#define KNN  64
#define EPSF 1e-7f
typedef unsigned long long ull;

// ------------------------- static scratch -------------------------
__device__ float g_px[NP], g_py[NP], g_pz[NP], g_vn[NP];
__device__ __align__(16) float4 g_pt4[NP];
__device__ ull   g_gmax, g_gmin;
__device__ int   g_idx[NP * KNN];
__device__ __align__(16) float g_feat[NP * KNN * 4];
__device__ __align__(16) float g_fd[NP * 4];
__device__ __align__(16) float g_emb[192 * NP];
__device__ __align__(16) float g_y1[64 * NP];
__device__ __align__(16) float g_y3[256 * NP];
__device__ __align__(16) float g_y4[1024 * NP];
__device__ float g_sc1[64],  g_sh1[64];
__device__ float g_sc2[192], g_sh2[192];
__device__ float g_sc3[256], g_sh3[256];
__device__ float g_sc4[1024], g_sh4[1024];

// ------------------------- f32x2 helpers -------------------------
__device__ __forceinline__ ull ffma2(ull a, ull b, ull c) {
    ull d;
    asm("fma.rn.f32x2 %0, %1, %2, %3;" : "=l"(d) : "l"(a), "l"(b), "l"(c));
    return d;
}
__device__ __forceinline__ ull pack2(float x, float y) {
    ull d;
    asm("mov.b64 %0, {%1, %2};" : "=l"(d) : "f"(x), "f"(y));
    return d;
}
__device__ __forceinline__ void unpack2(ull v, float& x, float& y) {
    asm("mov.b64 {%0, %1}, %2;" : "=f"(x), "=f"(y) : "l"(v));
}

// ------------------------- prep -------------------------
__global__ void prep_kernel(const float* __restrict__ pts) {
    int i = blockIdx.x * blockDim.x + threadIdx.x;
    if (i == 0) { g_gmax = 0ULL; g_gmin = ~0ULL; }
    if (i < 64) { g_sc2[i] = 1.0f; g_sh2[i] = 0.0f; }   // identity BN for emb_up rows
    if (i < NP) {
        float x = pts[3 * i], y = pts[3 * i + 1], z = pts[3 * i + 2];
        g_px[i] = x; g_py[i] = y; g_pz[i] = z;
        float rr = x * x + y * y + z * z;
        g_vn[i] = sqrtf(rr);
        g_pt4[i] = make_float4(x, y, z, rr);
    }
}

// ------------------------- KNN: threshold bound + exact rank select -------------------------
#define CAND_CAP 2048
__global__ void __launch_bounds__(256) knn_kernel() {
    const int i = blockIdx.x, tid = threadIdx.x;
    const int lane = tid & 31, warp = tid >> 5;
    __shared__ ull  cand[CAND_CAP];
    __shared__ int  wtmp[8];
    __shared__ unsigned swT[8];
    __shared__ int  wsum[16];

    float4 q4 = g_pt4[i];
    unsigned key[32];
#pragma unroll
    for (int s = 0; s < 32; s++) {
        float4 p = g_pt4[s * 256 + tid];
        float d = q4.w - 2.0f * (q4.x * p.x + q4.y * p.y + q4.z * p.z) + p.w;
        unsigned u = __float_as_uint(d);
        key[s] = u ^ ((u & 0x80000000u) ? 0xFFFFFFFFu : 0x80000000u);
    }

    unsigned lmin = 0xFFFFFFFFu;
#pragma unroll
    for (int s = 0; s < 32; s++) lmin = (key[s] < lmin) ? key[s] : lmin;
    unsigned val = lmin, Tw = 0;
#pragma unroll
    for (int r = 0; r < 8; r++) {
        unsigned m = __reduce_min_sync(0xFFFFFFFFu, val);
        Tw = m;
        unsigned ball = __ballot_sync(0xFFFFFFFFu, val == m);
        int leader = __ffs(ball) - 1;
        if (lane == leader) val = 0xFFFFFFFFu;
    }
    if (lane == 0) swT[warp] = Tw;
    __syncthreads();
    unsigned T = 0;
#pragma unroll
    for (int w = 0; w < 8; w++) T = (swT[w] > T) ? swT[w] : T;

    int c = 0;
#pragma unroll
    for (int s = 0; s < 32; s++) c += (key[s] <= T) ? 1 : 0;
    c = __reduce_add_sync(0xFFFFFFFFu, c);
    if (lane == 0) wtmp[warp] = c;
    __syncthreads();
    int na = 0, off = 0;
#pragma unroll
    for (int w = 0; w < 8; w++) { if (w < warp) off += wtmp[w]; na += wtmp[w]; }

    if (na > CAND_CAP) {
        unsigned v = 0u;
        for (int b = 31; b >= 0; b--) {
            unsigned cd = v | (1u << b);
            int cnt = 0;
#pragma unroll
            for (int s = 0; s < 32; s++) cnt += (key[s] < cd) ? 1 : 0;
            cnt = __reduce_add_sync(0xFFFFFFFFu, cnt);
            int bank = (b & 1) << 3;
            if (lane == 0) wsum[bank + warp] = cnt;
            __syncthreads();
            int tot = 0;
#pragma unroll
            for (int w = 0; w < 8; w++) tot += wsum[bank + w];
            if (tot < KNN) v = cd;
        }
        T = v;
        int c2 = 0;
#pragma unroll
        for (int s = 0; s < 32; s++) c2 += (key[s] <= T) ? 1 : 0;
        c2 = __reduce_add_sync(0xFFFFFFFFu, c2);
        __syncthreads();
        if (lane == 0) wtmp[warp] = c2;
        __syncthreads();
        na = 0; off = 0;
#pragma unroll
        for (int w = 0; w < 8; w++) { if (w < warp) off += wtmp[w]; na += wtmp[w]; }
        if (na > CAND_CAP) na = CAND_CAP;
    }

    unsigned lt = (1u << lane) - 1u;
    int o = off;
#pragma unroll
    for (int s = 0; s < 32; s++) {
        bool p = (key[s] <= T);
        unsigned mk = __ballot_sync(0xFFFFFFFFu, p);
        if (p) {
            int slot = o + __popc(mk & lt);
            if (slot < CAND_CAP)
                cand[slot] = (((ull)key[s]) << 32) | (unsigned)(s * 256 + tid);
        }
        o += __popc(mk);
    }
    __syncthreads();

    for (int c0 = tid; c0 < na; c0 += 256) {
        ull ct = cand[c0];
        int rank = 0;
        for (int j = 0; j < na; j++) rank += (cand[j] < ct) ? 1 : 0;
        if (rank < KNN) g_idx[i * KNN + rank] = (int)(ct & 0xFFFFFFFFu);
    }
}

// ------------------ per-query rotation-invariant KNN features ------------------
__global__ void __launch_bounds__(64) featknn_kernel() {
    int i = blockIdx.x, k = threadIdx.x;
    __shared__ float sx[64], sy[64], sz[64];
    __shared__ ull sred[64];
    __shared__ float rx[64], ry[64], rz[64];

    int j  = g_idx[i * KNN + k];
    int c0 = g_idx[i * KNN];
    float pcx = g_px[j] - g_px[c0];
    float pcy = g_py[j] - g_py[c0];
    float pcz = g_pz[j] - g_pz[c0];
    float vn  = sqrtf(pcx * pcx + pcy * pcy + pcz * pcz);
    sx[k] = pcx; sy[k] = pcy; sz[k] = pcz;
    rx[k] = pcx; ry[k] = pcy; rz[k] = pcz;
    sred[k] = (((ull)__float_as_uint(vn)) << 32) | (unsigned)(63 - k);
    __syncthreads();
    for (int off = 32; off > 0; off >>= 1) {
        if (k < off) {
            rx[k] += rx[k + off]; ry[k] += ry[k + off]; rz[k] += rz[k + off];
            ull o = sred[k + off];
            if (o > sred[k]) sred[k] = o;
        }
        __syncthreads();
    }
    int id1 = 63 - (int)(sred[0] & 0xFFFFFFFFu);
    float a1x = sx[id1], a1y = sy[id1], a1z = sz[id1];
    float n1 = sqrtf(a1x * a1x + a1y * a1y + a1z * a1z) + EPSF;
    a1x /= n1; a1y /= n1; a1z /= n1;
    float a2x = rx[0] * (1.0f / 64.0f), a2y = ry[0] * (1.0f / 64.0f), a2z = rz[0] * (1.0f / 64.0f);
    float n2 = sqrtf(a2x * a2x + a2y * a2y + a2z * a2z) + EPSF;
    a2x /= n2; a2y /= n2; a2z /= n2;
    float a3x = a1x + 1.5f * a2x, a3y = a1y + 1.5f * a2y, a3z = a1z + 1.5f * a2z;
    float n3 = sqrtf(a3x * a3x + a3y * a3y + a3z * a3z) + EPSF;
    a3x /= n3; a3y /= n3; a3z /= n3;

    float den = vn + EPSF;
    float f1 = (pcx * a1x + pcy * a1y + pcz * a1z) / den;
    float f2 = (pcx * a2x + pcy * a2y + pcz * a2z) / den;
    float f3 = (pcx * a3x + pcy * a3y + pcz * a3z) / den;
    *(float4*)(g_feat + (size_t)(i * KNN + k) * 4) = make_float4(f1, f2, f3, vn);
}

// ------------------ global axes reduce + fd ------------------
__global__ void __launch_bounds__(256) axes_reduce_kernel() {
    int t = blockIdx.x * blockDim.x + threadIdx.x;
    int lane = threadIdx.x & 31;
    unsigned b = __float_as_uint(g_vn[t]);
    ull pmx = (((ull)b) << 32) | (unsigned)(0xFFFFFFFFu - t);
    ull pmn = (((ull)b) << 32) | (unsigned)t;
#pragma unroll
    for (int off = 16; off > 0; off >>= 1) {
        ull ox = __shfl_down_sync(0xFFFFFFFFu, pmx, off);
        ull on = __shfl_down_sync(0xFFFFFFFFu, pmn, off);
        if (ox > pmx) pmx = ox;
        if (on < pmn) pmn = on;
    }
    if (lane == 0) { atomicMax(&g_gmax, pmx); atomicMin(&g_gmin, pmn); }
}

__global__ void fd_kernel() {
    int i = blockIdx.x * blockDim.x + threadIdx.x;
    if (i >= NP) return;
    int i1 = (int)(0xFFFFFFFFu - (unsigned)(g_gmax & 0xFFFFFFFFu));
    int i2 = (int)(g_gmin & 0xFFFFFFFFu);
    float n1 = g_vn[i1] + EPSF;
    float a1x = g_px[i1] / n1, a1y = g_py[i1] / n1, a1z = g_pz[i1] / n1;
    float n2 = g_vn[i2] + EPSF;
    float a2x = g_px[i2] / n2, a2y = g_py[i2] / n2, a2z = g_pz[i2] / n2;
    float a3x = a1x + 1.5f * a2x, a3y = a1y + 1.5f * a2y, a3z = a1z + 1.5f * a2z;
    float n3 = sqrtf(a3x * a3x + a3y * a3y + a3z * a3z) + EPSF;
    a3x /= n3; a3y /= n3; a3z /= n3;
    float x = g_px[i], y = g_py[i], z = g_pz[i], vn = g_vn[i];
    float den = vn + EPSF;
    float f1 = (x * a1x + y * a1y + z * a1z) / den;
    float f2 = (x * a2x + y * a2y + z * a2z) / den;
    float f3 = (x * a3x + y * a3y + z * a3z) / den;
    *(float4*)(g_fd + (size_t)i * 4) = make_float4(f1, f2, f3, vn);
}

// =================== mma.sync bf16 helpers (MLP) ===================
__device__ __forceinline__ void mma16816(float (&d)[4], const unsigned* a, const unsigned* b) {
    asm volatile(
        "mma.sync.aligned.m16n8k16.row.col.f32.bf16.bf16.f32 "
        "{%0,%1,%2,%3}, {%4,%5,%6,%7}, {%8,%9}, {%0,%1,%2,%3};"
        : "+f"(d[0]), "+f"(d[1]), "+f"(d[2]), "+f"(d[3])
        : "r"(a[0]), "r"(a[1]), "r"(a[2]), "r"(a[3]), "r"(b[0]), "r"(b[1]));
}
__device__ __forceinline__ void bfsplit2(float a, float b, unsigned& hi, unsigned& lo) {
    __nv_bfloat16 ha = __float2bfloat16(a), hb = __float2bfloat16(b);
    float ra = a - __bfloat162float(ha), rb = b - __bfloat162float(hb);
    __nv_bfloat16 la = __float2bfloat16(ra), lb = __float2bfloat16(rb);
    hi = ((unsigned)__bfloat16_as_ushort(hb) << 16) | (unsigned)__bfloat16_as_ushort(ha);
    lo = ((unsigned)__bfloat16_as_ushort(lb) << 16) | (unsigned)__bfloat16_as_ushort(la);
}

// SMEM layout (bytes): A hi/lo [128][BH] bf16, W hi/lo transposed [n=64][BH] bf16
#define BH 72
#define SM_AH 0
#define SM_AL (128 * BH * 2)            // 18432
#define SM_WH (2 * 128 * BH * 2)        // 36864
#define SM_WL (SM_WH + 64 * BH * 2)     // 46080
#define MLP3_SMEM (SM_WL + 64 * BH * 2 + 128)   // 55424

// ------------------ fused 5-layer MLP on mma.sync (bf16 hi/lo split) ------------------
// 1 block = 2 points; warp w owns output rows 16w..16w+15 (A rows are warp-private).
// Per layer: D[128,64] = A[128,Kc] @ W[Kc,64]; relu; re-split to bf16 hi/lo in place.
__global__ void __launch_bounds__(256) mlp_kernel(const float* __restrict__ gw0,
                                                  const float* __restrict__ gw1,
                                                  const float* __restrict__ gw2,
                                                  const float* __restrict__ gw3,
                                                  const float* __restrict__ gw4) {
    extern __shared__ char S[];
    int tid = threadIdx.x, lane = tid & 31, w = tid >> 5;
    int i0 = blockIdx.x * 2;

    // stage A layer-0: rows 0..127, cols 0..15 (cols 0..3 = feat, rest 0)
    for (int t = tid; t < 128 * 8; t += 256) {
        int m = t >> 3, cp = t & 7;
        int p = m >> 6, r = m & 63;
        float v0 = 0.f, v1 = 0.f;
        if (cp < 2) {
            float4 f = *(const float4*)(g_feat + (size_t)((i0 + p) * 64 + r) * 4);
            if (cp == 0) { v0 = f.x; v1 = f.y; } else { v0 = f.z; v1 = f.w; }
        }
        unsigned hi, lo; bfsplit2(v0, v1, hi, lo);
        *(unsigned*)(S + SM_AH + (m * BH + cp * 2) * 2) = hi;
        *(unsigned*)(S + SM_AL + (m * BH + cp * 2) * 2) = lo;
    }

    const float* gws[5] = {gw0, gw1, gw2, gw3, gw4};
    const int r0 = w * 16 + (lane >> 2);
    const int cb = (lane & 3) * 2;

#pragma unroll 1
    for (int layer = 0; layer < 5; layer++) {
        const float* gw = gws[layer];
        const int KcR = layer ? 64 : 4;         // real K
        const int kps = layer ? 32 : 8;         // staged col-pairs (K16/2)
        const int ksteps = layer ? 4 : 1;

        __syncthreads();                        // A staged / prior mma done before W overwrite
        for (int e = tid; e < 64 * kps; e += 256) {
            int n = e / kps, kp = e % kps;
            int k0 = kp * 2;
            float w0 = (k0 < KcR) ? gw[k0 * 64 + n] : 0.f;
            float w1 = (k0 + 1 < KcR) ? gw[(k0 + 1) * 64 + n] : 0.f;
            unsigned hi, lo; bfsplit2(w0, w1, hi, lo);
            *(unsigned*)(S + SM_WH + (n * BH + k0) * 2) = hi;
            *(unsigned*)(S + SM_WL + (n * BH + k0) * 2) = lo;
        }
        __syncthreads();

        float d[8][4];
#pragma unroll
        for (int nt = 0; nt < 8; nt++)
#pragma unroll
            for (int q = 0; q < 4; q++) d[nt][q] = 0.f;

        for (int ks = 0; ks < ksteps; ks++) {
            int c = cb + ks * 16;
            unsigned ah[4], al[4];
            ah[0] = *(const unsigned*)(S + SM_AH + (r0 * BH + c) * 2);
            ah[1] = *(const unsigned*)(S + SM_AH + ((r0 + 8) * BH + c) * 2);
            ah[2] = *(const unsigned*)(S + SM_AH + (r0 * BH + c + 8) * 2);
            ah[3] = *(const unsigned*)(S + SM_AH + ((r0 + 8) * BH + c + 8) * 2);
            al[0] = *(const unsigned*)(S + SM_AL + (r0 * BH + c) * 2);
            al[1] = *(const unsigned*)(S + SM_AL + ((r0 + 8) * BH + c) * 2);
            al[2] = *(const unsigned*)(S + SM_AL + (r0 * BH + c + 8) * 2);
            al[3] = *(const unsigned*)(S + SM_AL + ((r0 + 8) * BH + c + 8) * 2);
#pragma unroll
            for (int nt = 0; nt < 8; nt++) {
                int n0 = nt * 8 + (lane >> 2);
                unsigned bh[2], bl[2];
                bh[0] = *(const unsigned*)(S + SM_WH + (n0 * BH + c) * 2);
                bh[1] = *(const unsigned*)(S + SM_WH + (n0 * BH + c + 8) * 2);
                bl[0] = *(const unsigned*)(S + SM_WL + (n0 * BH + c) * 2);
                bl[1] = *(const unsigned*)(S + SM_WL + (n0 * BH + c + 8) * 2);
                mma16816(d[nt], ah, bh);
                mma16816(d[nt], ah, bl);
                mma16816(d[nt], al, bh);
            }
        }
        __syncthreads();                        // all warps done reading before rewrite

        if (layer < 4) {
#pragma unroll
            for (int nt = 0; nt < 8; nt++) {
                int c = nt * 8 + cb;
                float v0 = fmaxf(d[nt][0], 0.f), v1 = fmaxf(d[nt][1], 0.f);
                float v2 = fmaxf(d[nt][2], 0.f), v3 = fmaxf(d[nt][3], 0.f);
                unsigned hi, lo;
                bfsplit2(v0, v1, hi, lo);
                *(unsigned*)(S + SM_AH + (r0 * BH + c) * 2) = hi;
                *(unsigned*)(S + SM_AL + (r0 * BH + c) * 2) = lo;
                bfsplit2(v2, v3, hi, lo);
                *(unsigned*)(S + SM_AH + ((r0 + 8) * BH + c) * 2) = hi;
                *(unsigned*)(S + SM_AL + ((r0 + 8) * BH + c) * 2) = lo;
            }
        } else {
            float* F = (float*)S;               // [128][stride 68], overlays A region
#pragma unroll
            for (int nt = 0; nt < 8; nt++) {
                int c = nt * 8 + cb;
                F[r0 * 68 + c]       = fmaxf(d[nt][0], 0.f);
                F[r0 * 68 + c + 1]   = fmaxf(d[nt][1], 0.f);
                F[(r0 + 8) * 68 + c]     = fmaxf(d[nt][2], 0.f);
                F[(r0 + 8) * 68 + c + 1] = fmaxf(d[nt][3], 0.f);
            }
        }
    }
    __syncthreads();
    // final: column max over neighbors per point
    if (tid < 128) {
        const float* F = (const float*)S;
        int p = tid >> 6, c = tid & 63;
        float mx = 0.f;
        for (int r = 0; r < 64; r++) mx = fmaxf(mx, F[(p * 64 + r) * 68 + c]);
        g_emb[(i0 + p) * 64 + c] = mx;          // flat [n][64] == conv view [64][8192]
    }
}

// ------------------ GEMM with fused input-BN+ReLU (sc/sh staged in smem) --------
__global__ void __launch_bounds__(256) gemm_kernel(const float* __restrict__ W,
                                                   const float* __restrict__ X,
                                                   const float* __restrict__ bias,
                                                   float* __restrict__ Y,
                                                   int Kc,
                                                   const float* __restrict__ xsc,
                                                   const float* __restrict__ xsh) {
    __shared__ float sW[16][68];
    __shared__ float sX[16][132];
    __shared__ float ssc[256], ssh[256];
    int tid = threadIdx.x;
    int bm = blockIdx.y * 64, bn = blockIdx.x * 128;
    int tx = tid & 15, ty = tid >> 4;
    if (xsc) {
        for (int t = tid; t < Kc; t += 256) { ssc[t] = xsc[t]; ssh[t] = xsh[t]; }
    }
    ull acc[4][4];
#pragma unroll
    for (int u = 0; u < 4; u++)
#pragma unroll
        for (int q = 0; q < 4; q++) acc[u][q] = 0ULL;
    __syncthreads();

    for (int k0 = 0; k0 < Kc; k0 += 16) {
        for (int t = tid; t < 1024; t += 256) {
            int kk = t & 15, m = t >> 4;
            float val = 0.f;
            if (k0 + kk < Kc) val = W[(size_t)(bm + m) * Kc + k0 + kk];
            sW[kk][m] = val;
        }
        for (int t = tid; t < 2048; t += 256) {
            int n = t & 127, kk = t >> 7;
            float val = 0.f;
            if (k0 + kk < Kc) {
                val = X[(size_t)(k0 + kk) * NP + bn + n];
                if (xsc) val = fmaxf(val * ssc[k0 + kk] + ssh[k0 + kk], 0.f);
            }
            sX[kk][n] = val;
        }
        __syncthreads();
#pragma unroll
        for (int kk = 0; kk < 16; kk++) {
            float4 a = *(const float4*)&sW[kk][ty * 4];
            const ulonglong2* bx = (const ulonglong2*)&sX[kk][tx * 8];
            ulonglong2 b01 = bx[0];
            ulonglong2 b23 = bx[1];
            float av[4] = {a.x, a.y, a.z, a.w};
#pragma unroll
            for (int u = 0; u < 4; u++) {
                ull aa = pack2(av[u], av[u]);
                acc[u][0] = ffma2(aa, b01.x, acc[u][0]);
                acc[u][1] = ffma2(aa, b01.y, acc[u][1]);
                acc[u][2] = ffma2(aa, b23.x, acc[u][2]);
                acc[u][3] = ffma2(aa, b23.y, acc[u][3]);
            }
        }
        __syncthreads();
    }
    int m0 = bm + ty * 4;
#pragma unroll
    for (int u = 0; u < 4; u++) {
        float bv = bias[m0 + u];
        float o[8];
#pragma unroll
        for (int q = 0; q < 4; q++) {
            float vx, vy; unpack2(acc[u][q], vx, vy);
            o[q * 2] = vx + bv; o[q * 2 + 1] = vy + bv;
        }
        float* yrow = Y + (size_t)(m0 + u) * NP + bn + tx * 8;
        *(float4*)yrow       = make_float4(o[0], o[1], o[2], o[3]);
        *(float4*)(yrow + 4) = make_float4(o[4], o[5], o[6], o[7]);
    }
}

// ------------------ BatchNorm stats (one pass) ------------------
__global__ void __launch_bounds__(256) bn_stats_kernel(const float* __restrict__ Y,
                                                       const float* __restrict__ gamma,
                                                       const float* __restrict__ beta,
                                                       float* __restrict__ sc,
                                                       float* __restrict__ sh) {
    int ch = blockIdx.x, tid = threadIdx.x;
    const float4* row = (const float4*)(Y + (size_t)ch * NP);
    float s = 0.f, s2 = 0.f;
    for (int t = tid; t < NP / 4; t += 256) {
        float4 v = row[t];
        s  += v.x + v.y + v.z + v.w;
        s2 += v.x * v.x + v.y * v.y + v.z * v.z + v.w * v.w;
    }
    __shared__ float r1[256], r2[256];
    r1[tid] = s; r2[tid] = s2; __syncthreads();
    for (int off = 128; off > 0; off >>= 1) {
        if (tid < off) { r1[tid] += r1[tid + off]; r2[tid] += r2[tid + off]; }
        __syncthreads();
    }
    if (tid == 0) {
        float mu = r1[0] * (1.0f / NP);
        float var = r2[0] * (1.0f / NP) - mu * mu;
        var = fmaxf(var, 0.f);
        float s0 = gamma[ch] * rsqrtf(var + 1e-5f);
        sc[ch] = s0;
        sh[ch] = beta[ch] - mu * s0;
    }
}

__global__ void bn_apply_kernel(const float4* __restrict__ Yin, float4* __restrict__ Yout,
                                const float* __restrict__ sc, const float* __restrict__ sh) {
    int idx = blockIdx.x * blockDim.x + threadIdx.x;
    int ch = idx >> 11;
    float s0 = sc[ch], s1 = sh[ch];
    float4 v = Yin[idx];
    v.x = fmaxf(v.x * s0 + s1, 0.f);
    v.y = fmaxf(v.y * s0 + s1, 0.f);
    v.z = fmaxf(v.z * s0 + s1, 0.f);
    v.w = fmaxf(v.w * s0 + s1, 0.f);
    Yout[idx] = v;
}

// ------------------------- launch -------------------------
extern "C" void kernel_launch(void* const* d_in, const int* in_sizes, int n_in,
                              void* d_out, int out_size) {
    const float* pts  = (const float*)d_in[0];
    const float* gw0  = (const float*)d_in[1];
    const float* gw1  = (const float*)d_in[2];
    const float* gw2  = (const float*)d_in[3];
    const float* gw3  = (const float*)d_in[4];
    const float* gw4  = (const float*)d_in[5];
    const float* c1w  = (const float*)d_in[6];
    const float* c1b  = (const float*)d_in[7];
    const float* bn1g = (const float*)d_in[8];
    const float* bn1b = (const float*)d_in[9];
    const float* c2w  = (const float*)d_in[10];
    const float* c2b  = (const float*)d_in[11];
    const float* bn2g = (const float*)d_in[12];
    const float* bn2b = (const float*)d_in[13];
    const float* c3w  = (const float*)d_in[14];
    const float* c3b  = (const float*)d_in[15];
    const float* bn3g = (const float*)d_in[16];
    const float* bn3b = (const float*)d_in[17];
    const float* c4w  = (const float*)d_in[18];
    const float* c4b  = (const float*)d_in[19];
    const float* bn4g = (const float*)d_in[20];
    const float* bn4b = (const float*)d_in[21];
    float* out = (float*)d_out;

    float *p_fd, *p_emb, *p_y1, *p_y3, *p_y4;
    float *p_sc1, *p_sh1, *p_sc2, *p_sh2, *p_sc3, *p_sh3, *p_sc4, *p_sh4;
    cudaGetSymbolAddress((void**)&p_fd,  g_fd);
    cudaGetSymbolAddress((void**)&p_emb, g_emb);
    cudaGetSymbolAddress((void**)&p_y1,  g_y1);
    cudaGetSymbolAddress((void**)&p_y3,  g_y3);
    cudaGetSymbolAddress((void**)&p_y4,  g_y4);
    cudaGetSymbolAddress((void**)&p_sc1, g_sc1);
    cudaGetSymbolAddress((void**)&p_sh1, g_sh1);
    cudaGetSymbolAddress((void**)&p_sc2, g_sc2);
    cudaGetSymbolAddress((void**)&p_sh2, g_sh2);
    cudaGetSymbolAddress((void**)&p_sc3, g_sc3);
    cudaGetSymbolAddress((void**)&p_sh3, g_sh3);
    cudaGetSymbolAddress((void**)&p_sc4, g_sc4);
    cudaGetSymbolAddress((void**)&p_sh4, g_sh4);

    cudaFuncSetAttribute(mlp_kernel, cudaFuncAttributeMaxDynamicSharedMemorySize, MLP3_SMEM);

    prep_kernel<<<(NP + 255) / 256, 256>>>(pts);                    // 1
    knn_kernel<<<NP, 256>>>();                                      // 2
    featknn_kernel<<<NP, 64>>>();                                   // 3
    mlp_kernel<<<NP / 2, 256, MLP3_SMEM>>>(gw0, gw1, gw2, gw3, gw4);// 4 (ncu captures #4)
    axes_reduce_kernel<<<NP / 256, 256>>>();                        // 5
    fd_kernel<<<(NP + 255) / 256, 256>>>();                         // 6

    gemm_kernel<<<dim3(NP / 128, 1), 256>>>(c1w, p_fd, c1b, p_y1, 4, nullptr, nullptr);
    bn_stats_kernel<<<64, 256>>>(p_y1, bn1g, bn1b, p_sc1, p_sh1);
    gemm_kernel<<<dim3(NP / 128, 2), 256>>>(c2w, p_y1, c2b, p_emb + 64 * NP, 64, p_sc1, p_sh1);
    bn_stats_kernel<<<128, 256>>>(p_emb + 64 * NP, bn2g, bn2b, p_sc2 + 64, p_sh2 + 64);
    gemm_kernel<<<dim3(NP / 128, 4), 256>>>(c3w, p_emb, c3b, p_y3, 192, p_sc2, p_sh2);
    bn_stats_kernel<<<256, 256>>>(p_y3, bn3g, bn3b, p_sc3, p_sh3);
    gemm_kernel<<<dim3(NP / 128, 16), 256>>>(c4w, p_y3, c4b, p_y4, 256, p_sc3, p_sh3);
    bn_stats_kernel<<<1024, 256>>>(p_y4, bn4g, bn4b, p_sc4, p_sh4);
    bn_apply_kernel<<<1024 * NP / 1024, 256>>>((const float4*)p_y4, (float4*)out, p_sc4, p_sh4);

    (void)in_sizes; (void)n_in; (void)out_size;
}

// round 14
// speedup vs baseline: 2.1371x; 1.0370x over previous
#include <cuda_runtime.h>
#include <cuda_bf16.h>
#include <stdint.h>

#define NP   8192
#define KNN  64
#define EPSF 1e-7f
typedef unsigned long long ull;

// ------------------------- static scratch -------------------------
__device__ float g_px[NP], g_py[NP], g_pz[NP], g_vn[NP];
__device__ __align__(16) float4 g_pt4[NP];
__device__ ull   g_gmax, g_gmin;
__device__ int   g_idx[NP * KNN];
__device__ __align__(16) float g_feat[NP * KNN * 4];
__device__ __align__(16) float g_fd[NP * 4];
__device__ __align__(16) float g_emb[192 * NP];
__device__ __align__(16) float g_y1[64 * NP];
__device__ __align__(16) float g_y3[256 * NP];
__device__ __align__(16) float g_y4[1024 * NP];
__device__ float g_sc1[64],  g_sh1[64];
__device__ float g_sc2[192], g_sh2[192];
__device__ float g_sc3[256], g_sh3[256];
__device__ float g_sc4[1024], g_sh4[1024];

// ------------------------- f32x2 helpers -------------------------
__device__ __forceinline__ ull ffma2(ull a, ull b, ull c) {
    ull d;
    asm("fma.rn.f32x2 %0, %1, %2, %3;" : "=l"(d) : "l"(a), "l"(b), "l"(c));
    return d;
}
__device__ __forceinline__ ull pack2(float x, float y) {
    ull d;
    asm("mov.b64 %0, {%1, %2};" : "=l"(d) : "f"(x), "f"(y));
    return d;
}
__device__ __forceinline__ void unpack2(ull v, float& x, float& y) {
    asm("mov.b64 {%0, %1}, %2;" : "=f"(x), "=f"(y) : "l"(v));
}

// ------------------------- prep -------------------------
__global__ void prep_kernel(const float* __restrict__ pts) {
    int i = blockIdx.x * blockDim.x + threadIdx.x;
    if (i == 0) { g_gmax = 0ULL; g_gmin = ~0ULL; }
    if (i < 64) { g_sc2[i] = 1.0f; g_sh2[i] = 0.0f; }   // identity BN for emb_up rows
    if (i < NP) {
        float x = pts[3 * i], y = pts[3 * i + 1], z = pts[3 * i + 2];
        g_px[i] = x; g_py[i] = y; g_pz[i] = z;
        float rr = x * x + y * y + z * z;
        g_vn[i] = sqrtf(rr);
        g_pt4[i] = make_float4(x, y, z, rr);
    }
}

// ------------------------- KNN: threshold bound + exact rank select -------------------------
#define CAND_CAP 2048
__global__ void __launch_bounds__(256) knn_kernel() {
    const int i = blockIdx.x, tid = threadIdx.x;
    const int lane = tid & 31, warp = tid >> 5;
    __shared__ ull  cand[CAND_CAP];
    __shared__ int  wtmp[8];
    __shared__ unsigned swT[8];
    __shared__ int  wsum[16];

    float4 q4 = g_pt4[i];
    unsigned key[32];
#pragma unroll
    for (int s = 0; s < 32; s++) {
        float4 p = g_pt4[s * 256 + tid];
        float d = q4.w - 2.0f * (q4.x * p.x + q4.y * p.y + q4.z * p.z) + p.w;
        unsigned u = __float_as_uint(d);
        key[s] = u ^ ((u & 0x80000000u) ? 0xFFFFFFFFu : 0x80000000u);
    }

    unsigned lmin = 0xFFFFFFFFu;
#pragma unroll
    for (int s = 0; s < 32; s++) lmin = (key[s] < lmin) ? key[s] : lmin;
    unsigned val = lmin, Tw = 0;
#pragma unroll
    for (int r = 0; r < 8; r++) {
        unsigned m = __reduce_min_sync(0xFFFFFFFFu, val);
        Tw = m;
        unsigned ball = __ballot_sync(0xFFFFFFFFu, val == m);
        int leader = __ffs(ball) - 1;
        if (lane == leader) val = 0xFFFFFFFFu;
    }
    if (lane == 0) swT[warp] = Tw;
    __syncthreads();
    unsigned T = 0;
#pragma unroll
    for (int w = 0; w < 8; w++) T = (swT[w] > T) ? swT[w] : T;

    int c = 0;
#pragma unroll
    for (int s = 0; s < 32; s++) c += (key[s] <= T) ? 1 : 0;
    c = __reduce_add_sync(0xFFFFFFFFu, c);
    if (lane == 0) wtmp[warp] = c;
    __syncthreads();
    int na = 0, off = 0;
#pragma unroll
    for (int w = 0; w < 8; w++) { if (w < warp) off += wtmp[w]; na += wtmp[w]; }

    if (na > CAND_CAP) {
        unsigned v = 0u;
        for (int b = 31; b >= 0; b--) {
            unsigned cd = v | (1u << b);
            int cnt = 0;
#pragma unroll
            for (int s = 0; s < 32; s++) cnt += (key[s] < cd) ? 1 : 0;
            cnt = __reduce_add_sync(0xFFFFFFFFu, cnt);
            int bank = (b & 1) << 3;
            if (lane == 0) wsum[bank + warp] = cnt;
            __syncthreads();
            int tot = 0;
#pragma unroll
            for (int w = 0; w < 8; w++) tot += wsum[bank + w];
            if (tot < KNN) v = cd;
        }
        T = v;
        int c2 = 0;
#pragma unroll
        for (int s = 0; s < 32; s++) c2 += (key[s] <= T) ? 1 : 0;
        c2 = __reduce_add_sync(0xFFFFFFFFu, c2);
        __syncthreads();
        if (lane == 0) wtmp[warp] = c2;
        __syncthreads();
        na = 0; off = 0;
#pragma unroll
        for (int w = 0; w < 8; w++) { if (w < warp) off += wtmp[w]; na += wtmp[w]; }
        if (na > CAND_CAP) na = CAND_CAP;
    }

    unsigned lt = (1u << lane) - 1u;
    int o = off;
#pragma unroll
    for (int s = 0; s < 32; s++) {
        bool p = (key[s] <= T);
        unsigned mk = __ballot_sync(0xFFFFFFFFu, p);
        if (p) {
            int slot = o + __popc(mk & lt);
            if (slot < CAND_CAP)
                cand[slot] = (((ull)key[s]) << 32) | (unsigned)(s * 256 + tid);
        }
        o += __popc(mk);
    }
    __syncthreads();

    for (int c0 = tid; c0 < na; c0 += 256) {
        ull ct = cand[c0];
        int rank = 0;
        for (int j = 0; j < na; j++) rank += (cand[j] < ct) ? 1 : 0;
        if (rank < KNN) g_idx[i * KNN + rank] = (int)(ct & 0xFFFFFFFFu);
    }
}

// ------------------ per-query rotation-invariant KNN features ------------------
__global__ void __launch_bounds__(64) featknn_kernel() {
    int i = blockIdx.x, k = threadIdx.x;
    __shared__ float sx[64], sy[64], sz[64];
    __shared__ ull sred[64];
    __shared__ float rx[64], ry[64], rz[64];

    int j  = g_idx[i * KNN + k];
    int c0 = g_idx[i * KNN];
    float pcx = g_px[j] - g_px[c0];
    float pcy = g_py[j] - g_py[c0];
    float pcz = g_pz[j] - g_pz[c0];
    float vn  = sqrtf(pcx * pcx + pcy * pcy + pcz * pcz);
    sx[k] = pcx; sy[k] = pcy; sz[k] = pcz;
    rx[k] = pcx; ry[k] = pcy; rz[k] = pcz;
    sred[k] = (((ull)__float_as_uint(vn)) << 32) | (unsigned)(63 - k);
    __syncthreads();
    for (int off = 32; off > 0; off >>= 1) {
        if (k < off) {
            rx[k] += rx[k + off]; ry[k] += ry[k + off]; rz[k] += rz[k + off];
            ull o = sred[k + off];
            if (o > sred[k]) sred[k] = o;
        }
        __syncthreads();
    }
    int id1 = 63 - (int)(sred[0] & 0xFFFFFFFFu);
    float a1x = sx[id1], a1y = sy[id1], a1z = sz[id1];
    float n1 = sqrtf(a1x * a1x + a1y * a1y + a1z * a1z) + EPSF;
    a1x /= n1; a1y /= n1; a1z /= n1;
    float a2x = rx[0] * (1.0f / 64.0f), a2y = ry[0] * (1.0f / 64.0f), a2z = rz[0] * (1.0f / 64.0f);
    float n2 = sqrtf(a2x * a2x + a2y * a2y + a2z * a2z) + EPSF;
    a2x /= n2; a2y /= n2; a2z /= n2;
    float a3x = a1x + 1.5f * a2x, a3y = a1y + 1.5f * a2y, a3z = a1z + 1.5f * a2z;
    float n3 = sqrtf(a3x * a3x + a3y * a3y + a3z * a3z) + EPSF;
    a3x /= n3; a3y /= n3; a3z /= n3;

    float den = vn + EPSF;
    float f1 = (pcx * a1x + pcy * a1y + pcz * a1z) / den;
    float f2 = (pcx * a2x + pcy * a2y + pcz * a2z) / den;
    float f3 = (pcx * a3x + pcy * a3y + pcz * a3z) / den;
    *(float4*)(g_feat + (size_t)(i * KNN + k) * 4) = make_float4(f1, f2, f3, vn);
}

// ------------------ global axes reduce + fd ------------------
__global__ void __launch_bounds__(256) axes_reduce_kernel() {
    int t = blockIdx.x * blockDim.x + threadIdx.x;
    int lane = threadIdx.x & 31;
    unsigned b = __float_as_uint(g_vn[t]);
    ull pmx = (((ull)b) << 32) | (unsigned)(0xFFFFFFFFu - t);
    ull pmn = (((ull)b) << 32) | (unsigned)t;
#pragma unroll
    for (int off = 16; off > 0; off >>= 1) {
        ull ox = __shfl_down_sync(0xFFFFFFFFu, pmx, off);
        ull on = __shfl_down_sync(0xFFFFFFFFu, pmn, off);
        if (ox > pmx) pmx = ox;
        if (on < pmn) pmn = on;
    }
    if (lane == 0) { atomicMax(&g_gmax, pmx); atomicMin(&g_gmin, pmn); }
}

__global__ void fd_kernel() {
    int i = blockIdx.x * blockDim.x + threadIdx.x;
    if (i >= NP) return;
    int i1 = (int)(0xFFFFFFFFu - (unsigned)(g_gmax & 0xFFFFFFFFu));
    int i2 = (int)(g_gmin & 0xFFFFFFFFu);
    float n1 = g_vn[i1] + EPSF;
    float a1x = g_px[i1] / n1, a1y = g_py[i1] / n1, a1z = g_pz[i1] / n1;
    float n2 = g_vn[i2] + EPSF;
    float a2x = g_px[i2] / n2, a2y = g_py[i2] / n2, a2z = g_pz[i2] / n2;
    float a3x = a1x + 1.5f * a2x, a3y = a1y + 1.5f * a2y, a3z = a1z + 1.5f * a2z;
    float n3 = sqrtf(a3x * a3x + a3y * a3y + a3z * a3z) + EPSF;
    a3x /= n3; a3y /= n3; a3z /= n3;
    float x = g_px[i], y = g_py[i], z = g_pz[i], vn = g_vn[i];
    float den = vn + EPSF;
    float f1 = (x * a1x + y * a1y + z * a1z) / den;
    float f2 = (x * a2x + y * a2y + z * a2z) / den;
    float f3 = (x * a3x + y * a3y + z * a3z) / den;
    *(float4*)(g_fd + (size_t)i * 4) = make_float4(f1, f2, f3, vn);
}

// =================== mma.sync bf16 helpers (MLP) ===================
__device__ __forceinline__ void mma16816(float (&d)[4], const unsigned* a, const unsigned* b) {
    asm volatile(
        "mma.sync.aligned.m16n8k16.row.col.f32.bf16.bf16.f32 "
        "{%0,%1,%2,%3}, {%4,%5,%6,%7}, {%8,%9}, {%0,%1,%2,%3};"
        : "+f"(d[0]), "+f"(d[1]), "+f"(d[2]), "+f"(d[3])
        : "r"(a[0]), "r"(a[1]), "r"(a[2]), "r"(a[3]), "r"(b[0]), "r"(b[1]));
}
__device__ __forceinline__ void bfsplit2(float a, float b, unsigned& hi, unsigned& lo) {
    __nv_bfloat16 ha = __float2bfloat16(a), hb = __float2bfloat16(b);
    float ra = a - __bfloat162float(ha), rb = b - __bfloat162float(hb);
    __nv_bfloat16 la = __float2bfloat16(ra), lb = __float2bfloat16(rb);
    hi = ((unsigned)__bfloat16_as_ushort(hb) << 16) | (unsigned)__bfloat16_as_ushort(ha);
    lo = ((unsigned)__bfloat16_as_ushort(lb) << 16) | (unsigned)__bfloat16_as_ushort(la);
}

#define BH 72   // bf16 stride per weight row (conflict-free for fragment loads)

// ------------------ fused 5-layer MLP on mma.sync, activations in registers ------------------
// 1 block = 2 points; warp w owns output rows 16w..16w+15.
// D-output register layout == next layer's A-fragment layout, so activations
// (relu + bf16 hi/lo split) stay entirely in registers across layers.
__global__ void __launch_bounds__(256) mlp_kernel(const float* __restrict__ gw0,
                                                  const float* __restrict__ gw1,
                                                  const float* __restrict__ gw2,
                                                  const float* __restrict__ gw3,
                                                  const float* __restrict__ gw4) {
    __shared__ __align__(16) unsigned short WH[64 * BH];
    __shared__ __align__(16) unsigned short WL[64 * BH];
    __shared__ unsigned maxbuf[2][64];

    int tid = threadIdx.x, lane = tid & 31, w = tid >> 5;
    int i0 = blockIdx.x * 2;
    if (tid < 128) maxbuf[tid >> 6][tid & 63] = 0u;

    const int r0 = w * 16 + (lane >> 2);
    const int cb = (lane & 3) * 2;

    // A fragments (packed bf16 hi/lo) for the 4 k-chunks of the current layer
    unsigned aph[4][4], apl[4][4];
#pragma unroll
    for (int ks = 0; ks < 4; ks++)
#pragma unroll
        for (int j = 0; j < 4; j++) { aph[ks][j] = 0u; apl[ks][j] = 0u; }

    // layer-0 A: rows r0, r0+8; cols cb,cb+1 from feat (cols >= 4 are zero)
    {
        int m0 = r0, m1 = r0 + 8;
        float4 f0 = *(const float4*)(g_feat + (size_t)((i0 + (m0 >> 6)) * 64 + (m0 & 63)) * 4);
        float4 f1 = *(const float4*)(g_feat + (size_t)((i0 + (m1 >> 6)) * 64 + (m1 & 63)) * 4);
        float a00 = 0.f, a01 = 0.f, a10 = 0.f, a11 = 0.f;
        if (cb == 0) { a00 = f0.x; a01 = f0.y; a10 = f1.x; a11 = f1.y; }
        else if (cb == 2) { a00 = f0.z; a01 = f0.w; a10 = f1.z; a11 = f1.w; }
        bfsplit2(a00, a01, aph[0][0], apl[0][0]);
        bfsplit2(a10, a11, aph[0][1], apl[0][1]);
    }

    const float* gws[5] = {gw0, gw1, gw2, gw3, gw4};
    float d[8][4];

#pragma unroll 1
    for (int layer = 0; layer < 5; layer++) {
        const float* gw = gws[layer];
        const int KcR = layer ? 64 : 4;
        const int kps = layer ? 32 : 8;
        const int ksteps = layer ? 4 : 1;

        __syncthreads();   // all warps done reading previous W
        for (int e = tid; e < 64 * kps; e += 256) {
            int n = e / kps, kp = e % kps;
            int k0 = kp * 2;
            float w0 = (k0 < KcR) ? gw[k0 * 64 + n] : 0.f;
            float w1 = (k0 + 1 < KcR) ? gw[(k0 + 1) * 64 + n] : 0.f;
            unsigned hi, lo; bfsplit2(w0, w1, hi, lo);
            *(unsigned*)&WH[n * BH + k0] = hi;
            *(unsigned*)&WL[n * BH + k0] = lo;
        }
        __syncthreads();

#pragma unroll
        for (int nt = 0; nt < 8; nt++)
#pragma unroll
            for (int q = 0; q < 4; q++) d[nt][q] = 0.f;

        for (int ks = 0; ks < ksteps; ks++) {
            int c = cb + ks * 16;
#pragma unroll
            for (int nt = 0; nt < 8; nt++) {
                int n0 = nt * 8 + (lane >> 2);
                unsigned bh[2], bl[2];
                bh[0] = *(const unsigned*)&WH[n0 * BH + c];
                bh[1] = *(const unsigned*)&WH[n0 * BH + c + 8];
                bl[0] = *(const unsigned*)&WL[n0 * BH + c];
                bl[1] = *(const unsigned*)&WL[n0 * BH + c + 8];
                mma16816(d[nt], aph[ks], bh);
                mma16816(d[nt], aph[ks], bl);
                mma16816(d[nt], apl[ks], bh);
            }
        }

        if (layer < 4) {
            // relu + re-split in registers: d[2ks], d[2ks+1] -> A fragments of chunk ks
#pragma unroll
            for (int ks = 0; ks < 4; ks++) {
                float v0 = fmaxf(d[2 * ks][0], 0.f), v1 = fmaxf(d[2 * ks][1], 0.f);
                float v2 = fmaxf(d[2 * ks][2], 0.f), v3 = fmaxf(d[2 * ks][3], 0.f);
                float v4 = fmaxf(d[2 * ks + 1][0], 0.f), v5 = fmaxf(d[2 * ks + 1][1], 0.f);
                float v6 = fmaxf(d[2 * ks + 1][2], 0.f), v7 = fmaxf(d[2 * ks + 1][3], 0.f);
                bfsplit2(v0, v1, aph[ks][0], apl[ks][0]);
                bfsplit2(v2, v3, aph[ks][1], apl[ks][1]);
                bfsplit2(v4, v5, aph[ks][2], apl[ks][2]);
                bfsplit2(v6, v7, aph[ks][3], apl[ks][3]);
            }
        }
    }

    // final: relu + column-max over this warp's 16 rows, then cross-warp atomicMax
    float m0[8], m1[8];
#pragma unroll
    for (int nt = 0; nt < 8; nt++) {
        m0[nt] = fmaxf(fmaxf(d[nt][0], d[nt][2]), 0.f);
        m1[nt] = fmaxf(fmaxf(d[nt][1], d[nt][3]), 0.f);
    }
#pragma unroll
    for (int offs = 4; offs < 32; offs <<= 1) {
#pragma unroll
        for (int nt = 0; nt < 8; nt++) {
            m0[nt] = fmaxf(m0[nt], __shfl_xor_sync(0xFFFFFFFFu, m0[nt], offs));
            m1[nt] = fmaxf(m1[nt], __shfl_xor_sync(0xFFFFFFFFu, m1[nt], offs));
        }
    }
    if (lane < 4) {
        int p = w >> 2;
#pragma unroll
        for (int nt = 0; nt < 8; nt++) {
            atomicMax(&maxbuf[p][nt * 8 + lane * 2],     __float_as_uint(m0[nt]));
            atomicMax(&maxbuf[p][nt * 8 + lane * 2 + 1], __float_as_uint(m1[nt]));
        }
    }
    __syncthreads();
    if (tid < 128)
        g_emb[(i0 + (tid >> 6)) * 64 + (tid & 63)] = __uint_as_float(maxbuf[tid >> 6][tid & 63]);
}

// ------------------ GEMM with fused input-BN+ReLU (sc/sh staged in smem) --------
__global__ void __launch_bounds__(256) gemm_kernel(const float* __restrict__ W,
                                                   const float* __restrict__ X,
                                                   const float* __restrict__ bias,
                                                   float* __restrict__ Y,
                                                   int Kc,
                                                   const float* __restrict__ xsc,
                                                   const float* __restrict__ xsh) {
    __shared__ float sW[16][68];
    __shared__ float sX[16][132];
    __shared__ float ssc[256], ssh[256];
    int tid = threadIdx.x;
    int bm = blockIdx.y * 64, bn = blockIdx.x * 128;
    int tx = tid & 15, ty = tid >> 4;
    if (xsc) {
        for (int t = tid; t < Kc; t += 256) { ssc[t] = xsc[t]; ssh[t] = xsh[t]; }
    }
    ull acc[4][4];
#pragma unroll
    for (int u = 0; u < 4; u++)
#pragma unroll
        for (int q = 0; q < 4; q++) acc[u][q] = 0ULL;
    __syncthreads();

    for (int k0 = 0; k0 < Kc; k0 += 16) {
        for (int t = tid; t < 1024; t += 256) {
            int kk = t & 15, m = t >> 4;
            float val = 0.f;
            if (k0 + kk < Kc) val = W[(size_t)(bm + m) * Kc + k0 + kk];
            sW[kk][m] = val;
        }
        for (int t = tid; t < 2048; t += 256) {
            int n = t & 127, kk = t >> 7;
            float val = 0.f;
            if (k0 + kk < Kc) {
                val = X[(size_t)(k0 + kk) * NP + bn + n];
                if (xsc) val = fmaxf(val * ssc[k0 + kk] + ssh[k0 + kk], 0.f);
            }
            sX[kk][n] = val;
        }
        __syncthreads();
#pragma unroll
        for (int kk = 0; kk < 16; kk++) {
            float4 a = *(const float4*)&sW[kk][ty * 4];
            const ulonglong2* bx = (const ulonglong2*)&sX[kk][tx * 8];
            ulonglong2 b01 = bx[0];
            ulonglong2 b23 = bx[1];
            float av[4] = {a.x, a.y, a.z, a.w};
#pragma unroll
            for (int u = 0; u < 4; u++) {
                ull aa = pack2(av[u], av[u]);
                acc[u][0] = ffma2(aa, b01.x, acc[u][0]);
                acc[u][1] = ffma2(aa, b01.y, acc[u][1]);
                acc[u][2] = ffma2(aa, b23.x, acc[u][2]);
                acc[u][3] = ffma2(aa, b23.y, acc[u][3]);
            }
        }
        __syncthreads();
    }
    int m0 = bm + ty * 4;
#pragma unroll
    for (int u = 0; u < 4; u++) {
        float bv = bias[m0 + u];
        float o[8];
#pragma unroll
        for (int q = 0; q < 4; q++) {
            float vx, vy; unpack2(acc[u][q], vx, vy);
            o[q * 2] = vx + bv; o[q * 2 + 1] = vy + bv;
        }
        float* yrow = Y + (size_t)(m0 + u) * NP + bn + tx * 8;
        *(float4*)yrow       = make_float4(o[0], o[1], o[2], o[3]);
        *(float4*)(yrow + 4) = make_float4(o[4], o[5], o[6], o[7]);
    }
}

// ------------------ BatchNorm stats (one pass) ------------------
__global__ void __launch_bounds__(256) bn_stats_kernel(const float* __restrict__ Y,
                                                       const float* __restrict__ gamma,
                                                       const float* __restrict__ beta,
                                                       float* __restrict__ sc,
                                                       float* __restrict__ sh) {
    int ch = blockIdx.x, tid = threadIdx.x;
    const float4* row = (const float4*)(Y + (size_t)ch * NP);
    float s = 0.f, s2 = 0.f;
    for (int t = tid; t < NP / 4; t += 256) {
        float4 v = row[t];
        s  += v.x + v.y + v.z + v.w;
        s2 += v.x * v.x + v.y * v.y + v.z * v.z + v.w * v.w;
    }
    __shared__ float r1[256], r2[256];
    r1[tid] = s; r2[tid] = s2; __syncthreads();
    for (int off = 128; off > 0; off >>= 1) {
        if (tid < off) { r1[tid] += r1[tid + off]; r2[tid] += r2[tid + off]; }
        __syncthreads();
    }
    if (tid == 0) {
        float mu = r1[0] * (1.0f / NP);
        float var = r2[0] * (1.0f / NP) - mu * mu;
        var = fmaxf(var, 0.f);
        float s0 = gamma[ch] * rsqrtf(var + 1e-5f);
        sc[ch] = s0;
        sh[ch] = beta[ch] - mu * s0;
    }
}

__global__ void bn_apply_kernel(const float4* __restrict__ Yin, float4* __restrict__ Yout,
                                const float* __restrict__ sc, const float* __restrict__ sh) {
    int idx = blockIdx.x * blockDim.x + threadIdx.x;
    int ch = idx >> 11;
    float s0 = sc[ch], s1 = sh[ch];
    float4 v = Yin[idx];
    v.x = fmaxf(v.x * s0 + s1, 0.f);
    v.y = fmaxf(v.y * s0 + s1, 0.f);
    v.z = fmaxf(v.z * s0 + s1, 0.f);
    v.w = fmaxf(v.w * s0 + s1, 0.f);
    Yout[idx] = v;
}

// ------------------------- launch -------------------------
extern "C" void kernel_launch(void* const* d_in, const int* in_sizes, int n_in,
                              void* d_out, int out_size) {
    const float* pts  = (const float*)d_in[0];
    const float* gw0  = (const float*)d_in[1];
    const float* gw1  = (const float*)d_in[2];
    const float* gw2  = (const float*)d_in[3];
    const float* gw3  = (const float*)d_in[4];
    const float* gw4  = (const float*)d_in[5];
    const float* c1w  = (const float*)d_in[6];
    const float* c1b  = (const float*)d_in[7];
    const float* bn1g = (const float*)d_in[8];
    const float* bn1b = (const float*)d_in[9];
    const float* c2w  = (const float*)d_in[10];
    const float* c2b  = (const float*)d_in[11];
    const float* bn2g = (const float*)d_in[12];
    const float* bn2b = (const float*)d_in[13];
    const float* c3w  = (const float*)d_in[14];
    const float* c3b  = (const float*)d_in[15];
    const float* bn3g = (const float*)d_in[16];
    const float* bn3b = (const float*)d_in[17];
    const float* c4w  = (const float*)d_in[18];
    const float* c4b  = (const float*)d_in[19];
    const float* bn4g = (const float*)d_in[20];
    const float* bn4b = (const float*)d_in[21];
    float* out = (float*)d_out;

    float *p_fd, *p_emb, *p_y1, *p_y3, *p_y4;
    float *p_sc1, *p_sh1, *p_sc2, *p_sh2, *p_sc3, *p_sh3, *p_sc4, *p_sh4;
    cudaGetSymbolAddress((void**)&p_fd,  g_fd);
    cudaGetSymbolAddress((void**)&p_emb, g_emb);
    cudaGetSymbolAddress((void**)&p_y1,  g_y1);
    cudaGetSymbolAddress((void**)&p_y3,  g_y3);
    cudaGetSymbolAddress((void**)&p_y4,  g_y4);
    cudaGetSymbolAddress((void**)&p_sc1, g_sc1);
    cudaGetSymbolAddress((void**)&p_sh1, g_sh1);
    cudaGetSymbolAddress((void**)&p_sc2, g_sc2);
    cudaGetSymbolAddress((void**)&p_sh2, g_sh2);
    cudaGetSymbolAddress((void**)&p_sc3, g_sc3);
    cudaGetSymbolAddress((void**)&p_sh3, g_sh3);
    cudaGetSymbolAddress((void**)&p_sc4, g_sc4);
    cudaGetSymbolAddress((void**)&p_sh4, g_sh4);

    prep_kernel<<<(NP + 255) / 256, 256>>>(pts);                    // 1
    knn_kernel<<<NP, 256>>>();                                      // 2
    featknn_kernel<<<NP, 64>>>();                                   // 3
    mlp_kernel<<<NP / 2, 256>>>(gw0, gw1, gw2, gw3, gw4);           // 4 (ncu captures #4)
    axes_reduce_kernel<<<NP / 256, 256>>>();                        // 5
    fd_kernel<<<(NP + 255) / 256, 256>>>();                         // 6

    gemm_kernel<<<dim3(NP / 128, 1), 256>>>(c1w, p_fd, c1b, p_y1, 4, nullptr, nullptr);
    bn_stats_kernel<<<64, 256>>>(p_y1, bn1g, bn1b, p_sc1, p_sh1);
    gemm_kernel<<<dim3(NP / 128, 2), 256>>>(c2w, p_y1, c2b, p_emb + 64 * NP, 64, p_sc1, p_sh1);
    bn_stats_kernel<<<128, 256>>>(p_emb + 64 * NP, bn2g, bn2b, p_sc2 + 64, p_sh2 + 64);
    gemm_kernel<<<dim3(NP / 128, 4), 256>>>(c3w, p_emb, c3b, p_y3, 192, p_sc2, p_sh2);
    bn_stats_kernel<<<256, 256>>>(p_y3, bn3g, bn3b, p_sc3, p_sh3);
    gemm_kernel<<<dim3(NP / 128, 16), 256>>>(c4w, p_y3, c4b, p_y4, 256, p_sc3, p_sh3);
    bn_stats_kernel<<<1024, 256>>>(p_y4, bn4g, bn4b, p_sc4, p_sh4);
    bn_apply_kernel<<<1024 * NP / 1024, 256>>>((const float4*)p_y4, (float4*)out, p_sc4, p_sh4);

    (void)in_sizes; (void)n_in; (void)out_size;
}